// round 3
// baseline (speedup 1.0000x reference)
#include <cuda_runtime.h>
#include <cuda_bf16.h>
#include <cstdint>

// Fixed shapes
#define BB 4
#define CC 256
#define PP 1024
#define NK 8192
#define AA 64
#define PVSPLIT 4
#define TQ 32          // queries per block
#define KCH 16         // keys per chunk

// -------- device scratch (tf32-rounded bit patterns stored as float) --------
__device__ float g_q[BB * PP * AA];                   //  1 MB
__device__ float g_k[BB * NK * AA];                   //  8 MB
__device__ float g_v[BB * NK * CC];                   // 32 MB
__device__ float g_peq[PP * AA];
__device__ float g_pek[PP * AA];
__device__ float g_part[PVSPLIT * BB * PP * CC];      // 16 MB split-K partials

// -------- helpers --------
__device__ __forceinline__ uint32_t f2tf(float f) {
    uint32_t r;
    asm("cvt.rna.tf32.f32 %0, %1;" : "=r"(r) : "f"(f));
    return r;
}
__device__ __forceinline__ void mma8(float* c, const uint32_t* a, const uint32_t* b) {
    asm volatile("mma.sync.aligned.m16n8k8.row.col.f32.tf32.tf32.f32 "
                 "{%0,%1,%2,%3}, {%4,%5,%6,%7}, {%8,%9}, {%0,%1,%2,%3};"
                 : "+f"(c[0]), "+f"(c[1]), "+f"(c[2]), "+f"(c[3])
                 : "r"(a[0]), "r"(a[1]), "r"(a[2]), "r"(a[3]), "r"(b[0]), "r"(b[1]));
}
__device__ __forceinline__ uint4 cvt4(float4 v) {
    uint4 r;
    r.x = f2tf(v.x); r.y = f2tf(v.y); r.z = f2tf(v.z); r.w = f2tf(v.w);
    return r;
}
__device__ __forceinline__ void cp_async16(uint32_t dst, const void* src) {
    asm volatile("cp.async.cg.shared.global [%0], [%1], 16;" :: "r"(dst), "l"(src));
}
#define CP_COMMIT() asm volatile("cp.async.commit_group;")
template<int N> __device__ __forceinline__ void cp_wait() {
    asm volatile("cp.async.wait_group %0;" :: "n"(N));
}

// ============================================================================
// Kernel 1: positional-encoding projections pe_q / pe_k  [1024, 64] (fp32)
// ============================================================================
__global__ void pe_proj_kernel(const float* __restrict__ Wpx, const float* __restrict__ bpx,
                               const float* __restrict__ Wpy, const float* __restrict__ bpy) {
    int p = blockIdx.x;
    int y = p >> 5, x = p & 31;
    const float* W = blockIdx.y ? Wpy : Wpx;
    const float* bb = blockIdx.y ? bpy : bpx;
    float* outp = blockIdx.y ? g_pek : g_peq;

    __shared__ float pe[CC];
    int c = threadIdx.x;
    {
        int pos = (c < 128) ? y : x;
        int idx = (c < 128) ? c : (c - 128);
        int j = idx >> 1;
        float ang = (float)pos * expf(-logf(10000.0f) * (float)j / 64.0f);
        pe[c] = (idx & 1) ? cosf(ang) : sinf(ang);
    }
    __syncthreads();
    if (c < AA) {
        float s = 0.0f;
        #pragma unroll 8
        for (int i = 0; i < CC; i++) s += pe[i] * W[c * CC + i];
        outp[p * AA + c] = s + bb[c];
    }
}

// ============================================================================
// Kernel 2: tf32 projection GEMM; outputs tf32-ROUNDED bit patterns.
//   C[z][m][n] = tf32( sum_c A[z][c][m]*W[n][c] + bias[n] (+ extra[m][n]) )
// ============================================================================
__global__ __launch_bounds__(256) void proj_mma(const float* __restrict__ A,
                                                const float* __restrict__ W,
                                                const float* __restrict__ bias,
                                                int N, int mode) {
    __shared__ uint32_t As[32][136];
    __shared__ uint32_t Ws[64][36];

    float* C;
    const float* extra;
    if (mode == 0)      { C = g_q; extra = g_peq; }
    else if (mode == 1) { C = g_k; extra = g_pek; }
    else                { C = g_v; extra = nullptr; }

    int z = blockIdx.z;
    A += (size_t)z * CC * PP;
    C += (size_t)z * PP * N;
    int m0 = blockIdx.x * 128, n0 = blockIdx.y * 64;

    int tid = threadIdx.x;
    int wid = tid >> 5;
    int g = (tid >> 2) & 7, tg = tid & 3;
    int mbase = (wid >> 1) * 32;
    int nbase = (wid & 1) * 32;

    float acc[2][4][4];
    #pragma unroll
    for (int i = 0; i < 2; i++)
        #pragma unroll
        for (int j = 0; j < 4; j++)
            #pragma unroll
            for (int r = 0; r < 4; r++) acc[i][j][r] = 0.0f;

    for (int c0 = 0; c0 < CC; c0 += 32) {
        #pragma unroll
        for (int i = 0; i < 4; i++) {
            int idx = i * 256 + tid;
            int row = idx >> 5, c4 = idx & 31;
            float4 v = *(const float4*)&A[(size_t)(c0 + row) * PP + m0 + c4 * 4];
            *(uint4*)&As[row][c4 * 4] = cvt4(v);
        }
        #pragma unroll
        for (int i = 0; i < 2; i++) {
            int idx = i * 256 + tid;
            int row = idx >> 3, c4 = idx & 7;
            float4 v = *(const float4*)&W[(size_t)(n0 + row) * CC + c0 + c4 * 4];
            *(uint4*)&Ws[row][c4 * 4] = cvt4(v);
        }
        __syncthreads();

        #pragma unroll
        for (int ks = 0; ks < 4; ks++) {
            int k0 = ks * 8;
            uint32_t af[2][4], bf[4][2];
            #pragma unroll
            for (int mt = 0; mt < 2; mt++) {
                int mr = mbase + mt * 16;
                af[mt][0] = As[k0 + tg][mr + g];
                af[mt][1] = As[k0 + tg][mr + g + 8];
                af[mt][2] = As[k0 + tg + 4][mr + g];
                af[mt][3] = As[k0 + tg + 4][mr + g + 8];
            }
            #pragma unroll
            for (int nt = 0; nt < 4; nt++) {
                int nr = nbase + nt * 8;
                bf[nt][0] = Ws[nr + g][k0 + tg];
                bf[nt][1] = Ws[nr + g][k0 + tg + 4];
            }
            #pragma unroll
            for (int mt = 0; mt < 2; mt++)
                #pragma unroll
                for (int nt = 0; nt < 4; nt++)
                    mma8(acc[mt][nt], af[mt], bf[nt]);
        }
        __syncthreads();
    }

    #pragma unroll
    for (int mt = 0; mt < 2; mt++) {
        int r0 = m0 + mbase + mt * 16 + g;
        #pragma unroll
        for (int nt = 0; nt < 4; nt++) {
            int col = n0 + nbase + nt * 8 + 2 * tg;
            float b0 = bias[col], b1 = bias[col + 1];
            float e00 = 0, e01 = 0, e10 = 0, e11 = 0;
            if (mode < 2) {
                e00 = extra[(r0)     * AA + col]; e01 = extra[(r0)     * AA + col + 1];
                e10 = extra[(r0 + 8) * AA + col]; e11 = extra[(r0 + 8) * AA + col + 1];
            }
            *(float2*)&C[(size_t)r0 * N + col] = make_float2(
                __uint_as_float(f2tf(acc[mt][nt][0] + b0 + e00)),
                __uint_as_float(f2tf(acc[mt][nt][1] + b1 + e01)));
            *(float2*)&C[(size_t)(r0 + 8) * N + col] = make_float2(
                __uint_as_float(f2tf(acc[mt][nt][2] + b0 + e10)),
                __uint_as_float(f2tf(acc[mt][nt][3] + b1 + e11)));
        }
    }
}

// ============================================================================
// Kernel 3: FUSED attention. Batch-softmax is local per (q,k), so one block
// handles all 4 batches for a 32-query group: rows = 4b x 32q = 128.
// Grid (32 q-groups, 4 k-splits), 512 threads (16 warps).
// Per 16-key chunk (double-buffered cp.async K+V from L2):
//   QK mma (8m x 2n warps) -> stage S -> batch softmax (P as tf32 bits in smem)
//   -> PV mma (4b x 4c warps), acc resident in regs across all chunks.
// ============================================================================
#define VS_BUF (4 * KCH * 260)      // 16640 uints per buffer
#define KS_BUF (4 * KCH * 68)       // 4352
#define QS_OFF (2 * VS_BUF + 2 * KS_BUF)
#define SS_OFF (QS_OFF + 128 * 68)
#define SMEM_UINTS (SS_OFF + 128 * 20)   // 53248 uints = 212992 B

__global__ __launch_bounds__(512, 1) void attn_fused() {
    extern __shared__ uint32_t dsm[];
    uint32_t* Qs  = dsm + QS_OFF;           // [128 rows][68]
    float*    Ssm = (float*)(dsm + SS_OFF); // [128 rows][20]
    uint32_t  smem_base = (uint32_t)__cvta_generic_to_shared(dsm);

    const int tid = threadIdx.x;
    const int wid = tid >> 5;
    const int g = (tid >> 2) & 7, tg = tid & 3;
    const int qbase = blockIdx.x * TQ;
    const int split = blockIdx.y;
    const int kstart = split * (NK / PVSPLIT);
    const int NCHUNK = (NK / PVSPLIT) / KCH;   // 128

    // ---- load Q tile (tf32 bits): rows (b*32+q) x 64 ----
    #pragma unroll
    for (int j = 0; j < 4; j++) {
        int f = j * 512 + tid;
        int row = f >> 4, a4 = f & 15;
        int b = row >> 5, q = row & 31;
        uint4 v = *(const uint4*)&g_q[(size_t)((b << 10) + qbase + q) * AA + a4 * 4];
        *(uint4*)&Qs[row * 68 + a4 * 4] = v;
    }

    // ---- prefetch helper (chunk c into buffer buf) ----
    auto prefetch = [&](int c, int buf) {
        int kbase = kstart + c * KCH;
        // K: 4b x 16k x 64a -> 1024 uint4
        #pragma unroll
        for (int j = 0; j < 2; j++) {
            int f = j * 512 + tid;
            int row = f >> 4, a4 = f & 15;          // row = b*16+kk
            int b = row >> 4, kk = row & 15;
            uint32_t dst = smem_base + (2 * VS_BUF + buf * KS_BUF + row * 68 + a4 * 4) * 4;
            cp_async16(dst, &g_k[(size_t)((b << 13) + kbase + kk) * AA + a4 * 4]);
        }
        // V: 4b x 16k x 256c -> 4096 uint4
        #pragma unroll
        for (int j = 0; j < 8; j++) {
            int f = j * 512 + tid;
            int row = f >> 6, c4 = f & 63;
            int b = row >> 4, kk = row & 15;
            uint32_t dst = smem_base + (buf * VS_BUF + row * 260 + c4 * 4) * 4;
            cp_async16(dst, &g_v[(size_t)((b << 13) + kbase + kk) * CC + c4 * 4]);
        }
    };

    float acc[2][8][4];    // PV accumulators: warp (b, c-slice): 32q x 64c
    #pragma unroll
    for (int i = 0; i < 2; i++)
        #pragma unroll
        for (int j = 0; j < 8; j++)
            #pragma unroll
            for (int r = 0; r < 4; r++) acc[i][j][r] = 0.0f;

    // QK warp mapping: 8 m-warps x 2 n-warps
    const int wm = wid >> 1, wn = wid & 1;
    const int qk_b = wm >> 1;
    const int srow0 = wm * 16;
    // PV warp mapping: 4 b x 4 c-slices
    const int pv_b = wid >> 2;
    const int c0 = (wid & 3) * 64;

    prefetch(0, 0);
    CP_COMMIT();

    for (int ch = 0; ch < NCHUNK; ch++) {
        int buf = ch & 1;
        if (ch + 1 < NCHUNK) {
            prefetch(ch + 1, (ch + 1) & 1);
            CP_COMMIT();
            cp_wait<1>();
        } else {
            cp_wait<0>();
        }
        __syncthreads();   // chunk ready (also covers Qs on first iter)

        const uint32_t* Ks = dsm + 2 * VS_BUF + buf * KS_BUF;
        const uint32_t* Vs = dsm + buf * VS_BUF;

        // ---- QK: S[b][32q][16k], warp does 16 rows x 8 keys ----
        {
            float as[4] = {0, 0, 0, 0};
            int krow = (qk_b * 16 + wn * 8 + g) * 68;
            #pragma unroll
            for (int ks = 0; ks < 8; ks++) {
                int k0 = ks * 8;
                uint32_t af[4], bf[2];
                af[0] = Qs[(srow0 + g)     * 68 + k0 + tg];
                af[1] = Qs[(srow0 + g + 8) * 68 + k0 + tg];
                af[2] = Qs[(srow0 + g)     * 68 + k0 + tg + 4];
                af[3] = Qs[(srow0 + g + 8) * 68 + k0 + tg + 4];
                bf[0] = Ks[krow + k0 + tg];
                bf[1] = Ks[krow + k0 + tg + 4];
                mma8(as, af, bf);
            }
            *(float2*)&Ssm[(srow0 + g)     * 20 + wn * 8 + 2 * tg] =
                make_float2(as[0] * 0.125f, as[1] * 0.125f);
            *(float2*)&Ssm[(srow0 + g + 8) * 20 + wn * 8 + 2 * tg] =
                make_float2(as[2] * 0.125f, as[3] * 0.125f);
        }
        __syncthreads();

        // ---- batch softmax: 512 sites (32q x 16k), 1 per thread ----
        {
            int q = tid >> 4, kk = tid & 15;
            float s0 = Ssm[(q)       * 20 + kk];
            float s1 = Ssm[(32 + q)  * 20 + kk];
            float s2 = Ssm[(64 + q)  * 20 + kk];
            float s3 = Ssm[(96 + q)  * 20 + kk];
            float m = fmaxf(fmaxf(s0, s1), fmaxf(s2, s3));
            float e0 = __expf(s0 - m), e1 = __expf(s1 - m);
            float e2 = __expf(s2 - m), e3 = __expf(s3 - m);
            float r = 1.0f / (e0 + e1 + e2 + e3);
            Ssm[(q)      * 20 + kk] = __uint_as_float(f2tf(e0 * r));
            Ssm[(32 + q) * 20 + kk] = __uint_as_float(f2tf(e1 * r));
            Ssm[(64 + q) * 20 + kk] = __uint_as_float(f2tf(e2 * r));
            Ssm[(96 + q) * 20 + kk] = __uint_as_float(f2tf(e3 * r));
        }
        __syncthreads();

        // ---- PV: warp (pv_b, c0): P[b] 32q x 16k  @  V[b] 16k x 64c ----
        {
            const uint32_t* Pu = (const uint32_t*)Ssm;
            #pragma unroll
            for (int ks = 0; ks < 2; ks++) {
                int k0 = ks * 8;
                uint32_t af[2][4], bf[8][2];
                #pragma unroll
                for (int mt = 0; mt < 2; mt++) {
                    int r0 = (pv_b * 32 + mt * 16 + g) * 20;
                    af[mt][0] = Pu[r0 + k0 + tg];
                    af[mt][1] = Pu[r0 + 160 + k0 + tg];       // +8 rows
                    af[mt][2] = Pu[r0 + k0 + tg + 4];
                    af[mt][3] = Pu[r0 + 160 + k0 + tg + 4];
                }
                int vb0 = (pv_b * 16 + k0 + tg) * 260 + c0;
                int vb1 = (pv_b * 16 + k0 + tg + 4) * 260 + c0;
                #pragma unroll
                for (int nt = 0; nt < 8; nt++) {
                    bf[nt][0] = Vs[vb0 + nt * 8 + g];
                    bf[nt][1] = Vs[vb1 + nt * 8 + g];
                }
                #pragma unroll
                for (int mt = 0; mt < 2; mt++)
                    #pragma unroll
                    for (int nt = 0; nt < 8; nt++)
                        mma8(acc[mt][nt], af[mt], bf[nt]);
            }
        }
        __syncthreads();   // free this buffer + Ssm for next chunk
    }

    // ---- write split partials ----
    float* part = g_part + (size_t)split * (BB * PP * CC);
    #pragma unroll
    for (int mt = 0; mt < 2; mt++) {
        int qg = qbase + mt * 16 + g;
        size_t base0 = ((size_t)(pv_b << 10) + qg) * CC;
        #pragma unroll
        for (int nt = 0; nt < 8; nt++) {
            int col = c0 + nt * 8 + 2 * tg;
            *(float2*)&part[base0 + col]            = make_float2(acc[mt][nt][0], acc[mt][nt][1]);
            *(float2*)&part[base0 + (size_t)8 * CC + col] = make_float2(acc[mt][nt][2], acc[mt][nt][3]);
        }
    }
}

// ============================================================================
// Kernel 4: deterministic 4-way split-K reduction into d_out ([b][p][c])
// ============================================================================
__global__ void reduce4(float* __restrict__ out) {
    int i = blockIdx.x * blockDim.x + threadIdx.x;
    const float4* p = (const float4*)g_part;
    const int plane = BB * PP * CC / 4;
    float4 s = p[i];
    #pragma unroll
    for (int sp = 1; sp < PVSPLIT; sp++) {
        float4 t = p[(size_t)sp * plane + i];
        s.x += t.x; s.y += t.y; s.z += t.z; s.w += t.w;
    }
    ((float4*)out)[i] = s;
}

// ============================================================================
extern "C" void kernel_launch(void* const* d_in, const int* in_sizes, int n_in,
                              void* d_out, int out_size) {
    const float* zx  = (const float*)d_in[0];
    const float* zy  = (const float*)d_in[1];
    const float* Wq  = (const float*)d_in[2];
    const float* bq  = (const float*)d_in[3];
    const float* Wpx = (const float*)d_in[4];
    const float* bpx = (const float*)d_in[5];
    const float* Wk  = (const float*)d_in[6];
    const float* bk  = (const float*)d_in[7];
    const float* Wpy = (const float*)d_in[8];
    const float* bpy = (const float*)d_in[9];
    const float* Wv  = (const float*)d_in[10];
    const float* bv  = (const float*)d_in[11];
    float* out = (float*)d_out;

    const int attn_smem = SMEM_UINTS * 4;   // 212992 B
    cudaFuncSetAttribute(attn_fused, cudaFuncAttributeMaxDynamicSharedMemorySize, attn_smem);

    pe_proj_kernel<<<dim3(PP, 2), CC>>>(Wpx, bpx, Wpy, bpy);
    proj_mma<<<dim3(8, 1, 4),  256>>>(zx, Wq, bq, 64, 0);    // q
    proj_mma<<<dim3(8, 1, 32), 256>>>(zy, Wk, bk, 64, 1);    // k
    proj_mma<<<dim3(8, 4, 32), 256>>>(zy, Wv, bv, 256, 2);   // v
    attn_fused<<<dim3(PP / TQ, PVSPLIT), 512, attn_smem>>>();
    reduce4<<<(BB * PP * CC / 4) / 256, 256>>>(out);
}

// round 4
// speedup vs baseline: 1.2678x; 1.2678x over previous
#include <cuda_runtime.h>
#include <cuda_bf16.h>
#include <cstdint>

// Fixed shapes
#define BB 4
#define CC 256
#define PP 1024
#define NK 8192
#define AA 64
#define PL (PP * NK)
#define PVSPLIT 4

// -------- device scratch (tf32-rounded bit patterns stored as float) --------
__device__ float g_q[BB * PP * AA];                   //  1 MB (tf32 bits)
__device__ float g_k[BB * NK * AA];                   //  8 MB (tf32 bits)
__device__ float g_v[BB * NK * CC];                   // 32 MB (tf32 bits)
__device__ float g_peq[PP * AA];
__device__ float g_pek[PP * AA];
__device__ float g_P[(size_t)BB * PL];                // 128 MB P (tf32 bits)
__device__ float g_part[PVSPLIT * BB * PP * CC];      // 16 MB split-K partials

// -------- helpers --------
__device__ __forceinline__ uint32_t f2tf(float f) {
    uint32_t r;
    asm("cvt.rna.tf32.f32 %0, %1;" : "=r"(r) : "f"(f));
    return r;
}
__device__ __forceinline__ void mma8(float* c, const uint32_t* a, const uint32_t* b) {
    asm volatile("mma.sync.aligned.m16n8k8.row.col.f32.tf32.tf32.f32 "
                 "{%0,%1,%2,%3}, {%4,%5,%6,%7}, {%8,%9}, {%0,%1,%2,%3};"
                 : "+f"(c[0]), "+f"(c[1]), "+f"(c[2]), "+f"(c[3])
                 : "r"(a[0]), "r"(a[1]), "r"(a[2]), "r"(a[3]), "r"(b[0]), "r"(b[1]));
}
__device__ __forceinline__ uint4 cvt4(float4 v) {
    uint4 r;
    r.x = f2tf(v.x); r.y = f2tf(v.y); r.z = f2tf(v.z); r.w = f2tf(v.w);
    return r;
}
__device__ __forceinline__ void cp_async16(uint32_t dst, const void* src) {
    asm volatile("cp.async.cg.shared.global [%0], [%1], 16;" :: "r"(dst), "l"(src));
}
#define CP_COMMIT() asm volatile("cp.async.commit_group;")
template<int N> __device__ __forceinline__ void cp_wait() {
    asm volatile("cp.async.wait_group %0;" :: "n"(N));
}

// ============================================================================
// Kernel 1: positional-encoding projections pe_q / pe_k  [1024, 64] (fp32)
// ============================================================================
__global__ void pe_proj_kernel(const float* __restrict__ Wpx, const float* __restrict__ bpx,
                               const float* __restrict__ Wpy, const float* __restrict__ bpy) {
    int p = blockIdx.x;
    int y = p >> 5, x = p & 31;
    const float* W = blockIdx.y ? Wpy : Wpx;
    const float* bb = blockIdx.y ? bpy : bpx;
    float* outp = blockIdx.y ? g_pek : g_peq;

    __shared__ float pe[CC];
    int c = threadIdx.x;
    {
        int pos = (c < 128) ? y : x;
        int idx = (c < 128) ? c : (c - 128);
        int j = idx >> 1;
        float ang = (float)pos * expf(-logf(10000.0f) * (float)j / 64.0f);
        pe[c] = (idx & 1) ? cosf(ang) : sinf(ang);
    }
    __syncthreads();
    if (c < AA) {
        float s = 0.0f;
        #pragma unroll 8
        for (int i = 0; i < CC; i++) s += pe[i] * W[c * CC + i];
        outp[p * AA + c] = s + bb[c];
    }
}

// ============================================================================
// Kernel 2: tf32 projection GEMM; outputs tf32-ROUNDED bit patterns.
// ============================================================================
__global__ __launch_bounds__(256) void proj_mma(const float* __restrict__ A,
                                                const float* __restrict__ W,
                                                const float* __restrict__ bias,
                                                int N, int mode) {
    __shared__ uint32_t As[32][136];
    __shared__ uint32_t Ws[64][36];

    float* C;
    const float* extra;
    if (mode == 0)      { C = g_q; extra = g_peq; }
    else if (mode == 1) { C = g_k; extra = g_pek; }
    else                { C = g_v; extra = nullptr; }

    int z = blockIdx.z;
    A += (size_t)z * CC * PP;
    C += (size_t)z * PP * N;
    int m0 = blockIdx.x * 128, n0 = blockIdx.y * 64;

    int tid = threadIdx.x;
    int wid = tid >> 5;
    int g = (tid >> 2) & 7, tg = tid & 3;
    int mbase = (wid >> 1) * 32;
    int nbase = (wid & 1) * 32;

    float acc[2][4][4];
    #pragma unroll
    for (int i = 0; i < 2; i++)
        #pragma unroll
        for (int j = 0; j < 4; j++)
            #pragma unroll
            for (int r = 0; r < 4; r++) acc[i][j][r] = 0.0f;

    for (int c0 = 0; c0 < CC; c0 += 32) {
        #pragma unroll
        for (int i = 0; i < 4; i++) {
            int idx = i * 256 + tid;
            int row = idx >> 5, c4 = idx & 31;
            float4 v = *(const float4*)&A[(size_t)(c0 + row) * PP + m0 + c4 * 4];
            *(uint4*)&As[row][c4 * 4] = cvt4(v);
        }
        #pragma unroll
        for (int i = 0; i < 2; i++) {
            int idx = i * 256 + tid;
            int row = idx >> 3, c4 = idx & 7;
            float4 v = *(const float4*)&W[(size_t)(n0 + row) * CC + c0 + c4 * 4];
            *(uint4*)&Ws[row][c4 * 4] = cvt4(v);
        }
        __syncthreads();

        #pragma unroll
        for (int ks = 0; ks < 4; ks++) {
            int k0 = ks * 8;
            uint32_t af[2][4], bf[4][2];
            #pragma unroll
            for (int mt = 0; mt < 2; mt++) {
                int mr = mbase + mt * 16;
                af[mt][0] = As[k0 + tg][mr + g];
                af[mt][1] = As[k0 + tg][mr + g + 8];
                af[mt][2] = As[k0 + tg + 4][mr + g];
                af[mt][3] = As[k0 + tg + 4][mr + g + 8];
            }
            #pragma unroll
            for (int nt = 0; nt < 4; nt++) {
                int nr = nbase + nt * 8;
                bf[nt][0] = Ws[nr + g][k0 + tg];
                bf[nt][1] = Ws[nr + g][k0 + tg + 4];
            }
            #pragma unroll
            for (int mt = 0; mt < 2; mt++)
                #pragma unroll
                for (int nt = 0; nt < 4; nt++)
                    mma8(acc[mt][nt], af[mt], bf[nt]);
        }
        __syncthreads();
    }

    #pragma unroll
    for (int mt = 0; mt < 2; mt++) {
        int r0 = m0 + mbase + mt * 16 + g;
        #pragma unroll
        for (int nt = 0; nt < 4; nt++) {
            int col = n0 + nbase + nt * 8 + 2 * tg;
            float b0 = bias[col], b1 = bias[col + 1];
            float e00 = 0, e01 = 0, e10 = 0, e11 = 0;
            if (mode < 2) {
                e00 = extra[(r0)     * AA + col]; e01 = extra[(r0)     * AA + col + 1];
                e10 = extra[(r0 + 8) * AA + col]; e11 = extra[(r0 + 8) * AA + col + 1];
            }
            *(float2*)&C[(size_t)r0 * N + col] = make_float2(
                __uint_as_float(f2tf(acc[mt][nt][0] + b0 + e00)),
                __uint_as_float(f2tf(acc[mt][nt][1] + b1 + e01)));
            *(float2*)&C[(size_t)(r0 + 8) * N + col] = make_float2(
                __uint_as_float(f2tf(acc[mt][nt][2] + b0 + e10)),
                __uint_as_float(f2tf(acc[mt][nt][3] + b1 + e11)));
        }
    }
}

// ============================================================================
// Kernel 3: QK^T + batch softmax fused, P written directly as tf32 bits.
// One block computes the SAME 64q x 64k tile for ALL 4 batches -> each thread
// holds the 4 batch scores per site in registers -> softmax is register-local.
// Grid (16, 128), 256 threads (8 warps as 2m x 4n), K-dim=64 resident.
// ============================================================================
#define QK_SMEM_UINTS (2 * 4 * 64 * 68)   // 34816 uints = 139264 B

__global__ __launch_bounds__(256) void qk_softmax() {
    extern __shared__ uint32_t sm[];
    uint32_t* Qs = sm;                  // [4][64][68]
    uint32_t* Ks = sm + 4 * 64 * 68;

    const int tid = threadIdx.x;
    const int wid = tid >> 5;
    const int g = (tid >> 2) & 7, tg = tid & 3;
    const int qbase = blockIdx.x * 64, kbase = blockIdx.y * 64;

    // load Q & K tiles for all 4 batches (already tf32 bits)
    #pragma unroll
    for (int j = 0; j < 16; j++) {
        int f = j * 256 + tid;
        int row = f >> 4, a4 = f & 15;
        int b = row >> 6, r = row & 63;
        *(uint4*)&Qs[row * 68 + a4 * 4] =
            *(const uint4*)&g_q[(size_t)((b << 10) + qbase + r) * AA + a4 * 4];
        *(uint4*)&Ks[row * 68 + a4 * 4] =
            *(const uint4*)&g_k[(size_t)((b << 13) + kbase + r) * AA + a4 * 4];
    }
    __syncthreads();

    const int wm = wid >> 2, wn = wid & 3;
    const int qrow0 = wm * 32, kcol0 = wn * 16;

    float acc[4][2][2][4];
    #pragma unroll
    for (int b = 0; b < 4; b++)
        #pragma unroll
        for (int i = 0; i < 2; i++)
            #pragma unroll
            for (int j = 0; j < 2; j++)
                #pragma unroll
                for (int r = 0; r < 4; r++) acc[b][i][j][r] = 0.0f;

    #pragma unroll
    for (int ks = 0; ks < 8; ks++) {
        int k0 = ks * 8;
        #pragma unroll
        for (int b = 0; b < 4; b++) {
            const uint32_t* Qb = Qs + b * 64 * 68;
            const uint32_t* Kb = Ks + b * 64 * 68;
            uint32_t af[2][4], bf[2][2];
            #pragma unroll
            for (int mt = 0; mt < 2; mt++) {
                int r = qrow0 + mt * 16 + g;
                af[mt][0] = Qb[r * 68 + k0 + tg];
                af[mt][1] = Qb[(r + 8) * 68 + k0 + tg];
                af[mt][2] = Qb[r * 68 + k0 + tg + 4];
                af[mt][3] = Qb[(r + 8) * 68 + k0 + tg + 4];
            }
            #pragma unroll
            for (int nt = 0; nt < 2; nt++) {
                int rr = kcol0 + nt * 8 + g;
                bf[nt][0] = Kb[rr * 68 + k0 + tg];
                bf[nt][1] = Kb[rr * 68 + k0 + tg + 4];
            }
            #pragma unroll
            for (int mt = 0; mt < 2; mt++)
                #pragma unroll
                for (int nt = 0; nt < 2; nt++)
                    mma8(acc[b][mt][nt], af[mt], bf[nt]);
        }
    }

    // register-local batch softmax + direct P write (tf32 bits)
    #pragma unroll
    for (int mt = 0; mt < 2; mt++) {
        int row_lo = qbase + qrow0 + mt * 16 + g;
        #pragma unroll
        for (int nt = 0; nt < 2; nt++) {
            int col = kbase + kcol0 + nt * 8 + 2 * tg;
            float p[4][4];   // [r][b]
            #pragma unroll
            for (int r = 0; r < 4; r++) {
                float s0 = acc[0][mt][nt][r] * 0.125f;
                float s1 = acc[1][mt][nt][r] * 0.125f;
                float s2 = acc[2][mt][nt][r] * 0.125f;
                float s3 = acc[3][mt][nt][r] * 0.125f;
                float m = fmaxf(fmaxf(s0, s1), fmaxf(s2, s3));
                float e0 = __expf(s0 - m), e1 = __expf(s1 - m);
                float e2 = __expf(s2 - m), e3 = __expf(s3 - m);
                float rv = 1.0f / (e0 + e1 + e2 + e3);
                p[r][0] = __uint_as_float(f2tf(e0 * rv));
                p[r][1] = __uint_as_float(f2tf(e1 * rv));
                p[r][2] = __uint_as_float(f2tf(e2 * rv));
                p[r][3] = __uint_as_float(f2tf(e3 * rv));
            }
            #pragma unroll
            for (int b = 0; b < 4; b++) {
                float* Pb = g_P + (size_t)b * PL;
                *(float2*)&Pb[(size_t)row_lo * NK + col] = make_float2(p[0][b], p[1][b]);
                *(float2*)&Pb[(size_t)(row_lo + 8) * NK + col] = make_float2(p[2][b], p[3][b]);
            }
        }
    }
}

// ============================================================================
// Kernel 4: O = P @ V, split-K=4, cp.async double-buffered, no cvt in loop.
// BM=128, BN=128, BK=32. 8 warps (4m x 2n). 2 CTAs/SM. grid (8, 2, 16).
// ============================================================================
#define PS_BUF (128 * 36)    // 4608 uints
#define VS_BUF (32 * 136)    // 4352 uints
#define PV_SMEM_UINTS (2 * PS_BUF + 2 * VS_BUF)   // 17920 uints = 71680 B

__global__ __launch_bounds__(256, 2) void pv_mma() {
    extern __shared__ uint32_t sm[];
    uint32_t smem_base = (uint32_t)__cvta_generic_to_shared(sm);

    int b = blockIdx.z >> 2;
    int split = blockIdx.z & 3;
    int m0 = blockIdx.x * 128, n0 = blockIdx.y * 128;
    int tid = threadIdx.x;
    int wid = tid >> 5;
    int g = (tid >> 2) & 7, tg = tid & 3;
    int mbase = (wid >> 1) * 32;
    int nbase = (wid & 1) * 64;

    const float* P = g_P + (size_t)b * PL;
    const float* V = g_v + (size_t)b * NK * CC;

    auto prefetch = [&](int kb, int buf) {
        #pragma unroll
        for (int j = 0; j < 4; j++) {
            int f = j * 256 + tid;
            {   // P tile [128 m][32 k]
                int row = f >> 3, c4 = f & 7;
                uint32_t dst = smem_base + (buf * PS_BUF + row * 36 + c4 * 4) * 4;
                cp_async16(dst, &P[(size_t)(m0 + row) * NK + kb + c4 * 4]);
            }
            {   // V tile [32 k][128 n]
                int row = f >> 5, c4 = f & 31;
                uint32_t dst = smem_base + (2 * PS_BUF + buf * VS_BUF + row * 136 + c4 * 4) * 4;
                cp_async16(dst, &V[(size_t)(kb + row) * CC + n0 + c4 * 4]);
            }
        }
    };

    float acc[2][8][4];
    #pragma unroll
    for (int i = 0; i < 2; i++)
        #pragma unroll
        for (int j = 0; j < 8; j++)
            #pragma unroll
            for (int r = 0; r < 4; r++) acc[i][j][r] = 0.0f;

    const int kstart = split * (NK / PVSPLIT);
    const int NIT = (NK / PVSPLIT) / 32;   // 64

    prefetch(kstart, 0);
    CP_COMMIT();

    for (int it = 0; it < NIT; it++) {
        int buf = it & 1;
        if (it + 1 < NIT) {
            prefetch(kstart + (it + 1) * 32, buf ^ 1);
            CP_COMMIT();
            cp_wait<1>();
        } else {
            cp_wait<0>();
        }
        __syncthreads();

        const uint32_t* Ps = sm + buf * PS_BUF;
        const uint32_t* Vs = sm + 2 * PS_BUF + buf * VS_BUF;

        #pragma unroll
        for (int ks = 0; ks < 4; ks++) {
            int k0 = ks * 8;
            uint32_t af[2][4], bf[8][2];
            #pragma unroll
            for (int mt = 0; mt < 2; mt++) {
                int mr = mbase + mt * 16 + g;
                af[mt][0] = Ps[mr * 36 + k0 + tg];
                af[mt][1] = Ps[(mr + 8) * 36 + k0 + tg];
                af[mt][2] = Ps[mr * 36 + k0 + tg + 4];
                af[mt][3] = Ps[(mr + 8) * 36 + k0 + tg + 4];
            }
            int vb0 = (k0 + tg) * 136 + nbase;
            int vb1 = (k0 + tg + 4) * 136 + nbase;
            #pragma unroll
            for (int nt = 0; nt < 8; nt++) {
                bf[nt][0] = Vs[vb0 + nt * 8 + g];
                bf[nt][1] = Vs[vb1 + nt * 8 + g];
            }
            #pragma unroll
            for (int mt = 0; mt < 2; mt++)
                #pragma unroll
                for (int nt = 0; nt < 8; nt++)
                    mma8(acc[mt][nt], af[mt], bf[nt]);
        }
        __syncthreads();
    }

    float* part = g_part + (size_t)split * (BB * PP * CC);
    #pragma unroll
    for (int mt = 0; mt < 2; mt++) {
        int r0 = m0 + mbase + mt * 16 + g;
        #pragma unroll
        for (int nt = 0; nt < 8; nt++) {
            int col = n0 + nbase + nt * 8 + 2 * tg;
            *(float2*)&part[(size_t)((b << 10) + r0) * CC + col] =
                make_float2(acc[mt][nt][0], acc[mt][nt][1]);
            *(float2*)&part[(size_t)((b << 10) + r0 + 8) * CC + col] =
                make_float2(acc[mt][nt][2], acc[mt][nt][3]);
        }
    }
}

// ============================================================================
// Kernel 5: deterministic 4-way split-K reduction into d_out ([b][p][c])
// ============================================================================
__global__ void reduce4(float* __restrict__ out) {
    int i = blockIdx.x * blockDim.x + threadIdx.x;
    const float4* p = (const float4*)g_part;
    const int plane = BB * PP * CC / 4;
    float4 s = p[i];
    #pragma unroll
    for (int sp = 1; sp < PVSPLIT; sp++) {
        float4 t = p[(size_t)sp * plane + i];
        s.x += t.x; s.y += t.y; s.z += t.z; s.w += t.w;
    }
    ((float4*)out)[i] = s;
}

// ============================================================================
extern "C" void kernel_launch(void* const* d_in, const int* in_sizes, int n_in,
                              void* d_out, int out_size) {
    const float* zx  = (const float*)d_in[0];
    const float* zy  = (const float*)d_in[1];
    const float* Wq  = (const float*)d_in[2];
    const float* bq  = (const float*)d_in[3];
    const float* Wpx = (const float*)d_in[4];
    const float* bpx = (const float*)d_in[5];
    const float* Wk  = (const float*)d_in[6];
    const float* bk  = (const float*)d_in[7];
    const float* Wpy = (const float*)d_in[8];
    const float* bpy = (const float*)d_in[9];
    const float* Wv  = (const float*)d_in[10];
    const float* bv  = (const float*)d_in[11];
    float* out = (float*)d_out;

    cudaFuncSetAttribute(qk_softmax, cudaFuncAttributeMaxDynamicSharedMemorySize,
                         QK_SMEM_UINTS * 4);
    cudaFuncSetAttribute(pv_mma, cudaFuncAttributeMaxDynamicSharedMemorySize,
                         PV_SMEM_UINTS * 4);

    pe_proj_kernel<<<dim3(PP, 2), CC>>>(Wpx, bpx, Wpy, bpy);
    proj_mma<<<dim3(8, 1, 4),  256>>>(zx, Wq, bq, 64, 0);    // q
    proj_mma<<<dim3(8, 1, 32), 256>>>(zy, Wk, bk, 64, 1);    // k
    proj_mma<<<dim3(8, 4, 32), 256>>>(zy, Wv, bv, 256, 2);   // v
    qk_softmax<<<dim3(PP / 64, NK / 64), 256, QK_SMEM_UINTS * 4>>>();
    pv_mma<<<dim3(8, 2, 16), 256, PV_SMEM_UINTS * 4>>>();
    reduce4<<<(BB * PP * CC / 4) / 256, 256>>>(out);
}

// round 5
// speedup vs baseline: 1.5225x; 1.2009x over previous
#include <cuda_runtime.h>
#include <cuda_bf16.h>
#include <cstdint>

// Fixed shapes
#define BB 4
#define CC 256
#define PP 1024
#define NK 8192
#define AA 64
#define PL (PP * NK)
#define PVSPLIT 4

// -------- device scratch --------
// bf16 pairs packed in uint32
__device__ unsigned g_q[BB * PP * AA / 2];            // 0.5 MB  [b][p][a/2]
__device__ unsigned g_k[BB * NK * AA / 2];            //  4 MB   [b][k][a/2]
__device__ unsigned g_vt[BB * CC * NK / 2];           // 16 MB   [b][c][k/2]  (V transposed)
__device__ unsigned g_P[(size_t)BB * PL / 2];         // 64 MB   [b][p][k/2]
__device__ float g_peq[PP * AA];
__device__ float g_pek[PP * AA];
__device__ float g_part[PVSPLIT * BB * PP * CC];      // 16 MB fp32 partials

// -------- helpers --------
__device__ __forceinline__ uint32_t f2tf(float f) {
    uint32_t r;
    asm("cvt.rna.tf32.f32 %0, %1;" : "=r"(r) : "f"(f));
    return r;
}
__device__ __forceinline__ unsigned pack_bf16(float lo, float hi) {
    unsigned r;
    asm("cvt.rn.bf16x2.f32 %0, %1, %2;" : "=r"(r) : "f"(hi), "f"(lo));
    return r;
}
// tf32 m16n8k8 (projections)
__device__ __forceinline__ void mma8(float* c, const uint32_t* a, const uint32_t* b) {
    asm volatile("mma.sync.aligned.m16n8k8.row.col.f32.tf32.tf32.f32 "
                 "{%0,%1,%2,%3}, {%4,%5,%6,%7}, {%8,%9}, {%0,%1,%2,%3};"
                 : "+f"(c[0]), "+f"(c[1]), "+f"(c[2]), "+f"(c[3])
                 : "r"(a[0]), "r"(a[1]), "r"(a[2]), "r"(a[3]), "r"(b[0]), "r"(b[1]));
}
// bf16 m16n8k16 (attention)
__device__ __forceinline__ void mma16(float* c, const unsigned* a, const unsigned* b) {
    asm volatile("mma.sync.aligned.m16n8k16.row.col.f32.bf16.bf16.f32 "
                 "{%0,%1,%2,%3}, {%4,%5,%6,%7}, {%8,%9}, {%0,%1,%2,%3};"
                 : "+f"(c[0]), "+f"(c[1]), "+f"(c[2]), "+f"(c[3])
                 : "r"(a[0]), "r"(a[1]), "r"(a[2]), "r"(a[3]), "r"(b[0]), "r"(b[1]));
}
__device__ __forceinline__ uint4 cvt4(float4 v) {
    uint4 r;
    r.x = f2tf(v.x); r.y = f2tf(v.y); r.z = f2tf(v.z); r.w = f2tf(v.w);
    return r;
}
__device__ __forceinline__ void cp_async16(uint32_t dst, const void* src) {
    asm volatile("cp.async.cg.shared.global [%0], [%1], 16;" :: "r"(dst), "l"(src));
}
#define CP_COMMIT() asm volatile("cp.async.commit_group;")
template<int N> __device__ __forceinline__ void cp_wait() {
    asm volatile("cp.async.wait_group %0;" :: "n"(N));
}

// ============================================================================
// Kernel 1: positional-encoding projections pe_q / pe_k  [1024, 64] (fp32)
// ============================================================================
__global__ void pe_proj_kernel(const float* __restrict__ Wpx, const float* __restrict__ bpx,
                               const float* __restrict__ Wpy, const float* __restrict__ bpy) {
    int p = blockIdx.x;
    int y = p >> 5, x = p & 31;
    const float* W = blockIdx.y ? Wpy : Wpx;
    const float* bb = blockIdx.y ? bpy : bpx;
    float* outp = blockIdx.y ? g_pek : g_peq;

    __shared__ float pe[CC];
    int c = threadIdx.x;
    {
        int pos = (c < 128) ? y : x;
        int idx = (c < 128) ? c : (c - 128);
        int j = idx >> 1;
        float ang = (float)pos * expf(-logf(10000.0f) * (float)j / 64.0f);
        pe[c] = (idx & 1) ? cosf(ang) : sinf(ang);
    }
    __syncthreads();
    if (c < AA) {
        float s = 0.0f;
        #pragma unroll 8
        for (int i = 0; i < CC; i++) s += pe[i] * W[c * CC + i];
        outp[p * AA + c] = s + bb[c];
    }
}

// ============================================================================
// Kernel 2: tf32 projection GEMM -> bf16 outputs.
// mode 0: q -> g_q (+pe), mode 1: k -> g_k (+pe), mode 2: v -> g_vt TRANSPOSED
// BM=128, BN=64, BK=32; z = (b, page).
// ============================================================================
__global__ __launch_bounds__(256) void proj_mma(const float* __restrict__ A,
                                                const float* __restrict__ W,
                                                const float* __restrict__ bias,
                                                int N, int mode) {
    __shared__ uint32_t As[32][136];
    __shared__ uint32_t Ws[64][36];

    int z = blockIdx.z;
    A += (size_t)z * CC * PP;
    int m0 = blockIdx.x * 128, n0 = blockIdx.y * 64;

    int tid = threadIdx.x;
    int wid = tid >> 5;
    int g = (tid >> 2) & 7, tg = tid & 3;
    int mbase = (wid >> 1) * 32;
    int nbase = (wid & 1) * 32;

    float acc[2][4][4];
    #pragma unroll
    for (int i = 0; i < 2; i++)
        #pragma unroll
        for (int j = 0; j < 4; j++)
            #pragma unroll
            for (int r = 0; r < 4; r++) acc[i][j][r] = 0.0f;

    for (int c0 = 0; c0 < CC; c0 += 32) {
        #pragma unroll
        for (int i = 0; i < 4; i++) {
            int idx = i * 256 + tid;
            int row = idx >> 5, c4 = idx & 31;
            float4 v = *(const float4*)&A[(size_t)(c0 + row) * PP + m0 + c4 * 4];
            *(uint4*)&As[row][c4 * 4] = cvt4(v);
        }
        #pragma unroll
        for (int i = 0; i < 2; i++) {
            int idx = i * 256 + tid;
            int row = idx >> 3, c4 = idx & 7;
            float4 v = *(const float4*)&W[(size_t)(n0 + row) * CC + c0 + c4 * 4];
            *(uint4*)&Ws[row][c4 * 4] = cvt4(v);
        }
        __syncthreads();

        #pragma unroll
        for (int ks = 0; ks < 4; ks++) {
            int k0 = ks * 8;
            uint32_t af[2][4], bf[4][2];
            #pragma unroll
            for (int mt = 0; mt < 2; mt++) {
                int mr = mbase + mt * 16;
                af[mt][0] = As[k0 + tg][mr + g];
                af[mt][1] = As[k0 + tg][mr + g + 8];
                af[mt][2] = As[k0 + tg + 4][mr + g];
                af[mt][3] = As[k0 + tg + 4][mr + g + 8];
            }
            #pragma unroll
            for (int nt = 0; nt < 4; nt++) {
                int nr = nbase + nt * 8;
                bf[nt][0] = Ws[nr + g][k0 + tg];
                bf[nt][1] = Ws[nr + g][k0 + tg + 4];
            }
            #pragma unroll
            for (int mt = 0; mt < 2; mt++)
                #pragma unroll
                for (int nt = 0; nt < 4; nt++)
                    mma8(acc[mt][nt], af[mt], bf[nt]);
        }
        __syncthreads();
    }

    if (mode < 2) {
        // q/k: write packed bf16 [m][n/2], add bias + pe
        const float* extra = (mode == 0) ? g_peq : g_pek;
        unsigned* C = (mode == 0 ? g_q : g_k) + (size_t)z * PP * (N / 2);
        #pragma unroll
        for (int mt = 0; mt < 2; mt++) {
            int r0 = m0 + mbase + mt * 16 + g;
            #pragma unroll
            for (int nt = 0; nt < 4; nt++) {
                int col = n0 + nbase + nt * 8 + 2 * tg;
                float b0 = bias[col], b1 = bias[col + 1];
                float e00 = extra[r0 * AA + col],       e01 = extra[r0 * AA + col + 1];
                float e10 = extra[(r0 + 8) * AA + col], e11 = extra[(r0 + 8) * AA + col + 1];
                C[r0 * (N / 2) + col / 2] =
                    pack_bf16(acc[mt][nt][0] + b0 + e00, acc[mt][nt][1] + b1 + e01);
                C[(r0 + 8) * (N / 2) + col / 2] =
                    pack_bf16(acc[mt][nt][2] + b0 + e10, acc[mt][nt][3] + b1 + e11);
            }
        }
    } else {
        // v: stage bf16 transposed tile [64 n][128 m] in smem, write g_vt coalesced
        __nv_bfloat16* Cs = (__nv_bfloat16*)&As[0][0];   // 64 x 132 bf16 (66-uint rows)
        #pragma unroll
        for (int mt = 0; mt < 2; mt++) {
            int r0 = mbase + mt * 16 + g;
            #pragma unroll
            for (int nt = 0; nt < 4; nt++) {
                int col = nbase + nt * 8 + 2 * tg;
                float b0 = bias[n0 + col], b1 = bias[n0 + col + 1];
                Cs[(col)     * 132 + r0]     = __float2bfloat16(acc[mt][nt][0] + b0);
                Cs[(col + 1) * 132 + r0]     = __float2bfloat16(acc[mt][nt][1] + b1);
                Cs[(col)     * 132 + r0 + 8] = __float2bfloat16(acc[mt][nt][2] + b0);
                Cs[(col + 1) * 132 + r0 + 8] = __float2bfloat16(acc[mt][nt][3] + b1);
            }
        }
        __syncthreads();
        int b = z >> 3, page = z & 7;
        const unsigned* Csu = (const unsigned*)Cs;
        #pragma unroll
        for (int j = 0; j < 16; j++) {
            int f = j * 256 + tid;
            int n = f >> 6, u = f & 63;
            g_vt[(size_t)(b * CC + n0 + n) * (NK / 2) + page * 512 + m0 / 2 + u] =
                Csu[n * 66 + u];
        }
    }
}

// ============================================================================
// Kernel 3: QK^T (bf16 m16n8k16) + register-local batch softmax -> P (bf16).
// Block: 64q x 64k tile for all 4 batches. Grid (16, 128), 256 threads.
// ============================================================================
#define QK_TILE (4 * 64 * 36)                 // per tensor, uints
#define QK_SMEM_BYTES (2 * QK_TILE * 4)       // 73728 B

__global__ __launch_bounds__(256) void qk_softmax() {
    extern __shared__ uint32_t sm[];
    uint32_t* Qs = sm;             // [4][64][36]
    uint32_t* Ks = sm + QK_TILE;

    const int tid = threadIdx.x;
    const int wid = tid >> 5;
    const int g = (tid >> 2) & 7, tg = tid & 3;
    const int qbase = blockIdx.x * 64, kbase = blockIdx.y * 64;

    #pragma unroll
    for (int j = 0; j < 8; j++) {
        int f = j * 256 + tid;
        int row = f >> 3, a4 = f & 7;       // 256 rows x 8 uint4
        int b = row >> 6, r = row & 63;
        *(uint4*)&Qs[row * 36 + a4 * 4] =
            *(const uint4*)&g_q[((b << 10) + qbase + r) * 32 + a4 * 4];
        *(uint4*)&Ks[row * 36 + a4 * 4] =
            *(const uint4*)&g_k[((b << 13) + kbase + r) * 32 + a4 * 4];
    }
    __syncthreads();

    const int wm = wid >> 2, wn = wid & 3;
    const int qrow0 = wm * 32, kcol0 = wn * 16;

    float acc[4][2][2][4];
    #pragma unroll
    for (int b = 0; b < 4; b++)
        #pragma unroll
        for (int i = 0; i < 2; i++)
            #pragma unroll
            for (int j = 0; j < 2; j++)
                #pragma unroll
                for (int r = 0; r < 4; r++) acc[b][i][j][r] = 0.0f;

    #pragma unroll
    for (int ks = 0; ks < 4; ks++) {
        int k0u = ks * 8;
        #pragma unroll
        for (int b = 0; b < 4; b++) {
            const uint32_t* Qb = Qs + b * 64 * 36;
            const uint32_t* Kb = Ks + b * 64 * 36;
            unsigned af[2][4], bf[2][2];
            #pragma unroll
            for (int mt = 0; mt < 2; mt++) {
                int r = qrow0 + mt * 16 + g;
                af[mt][0] = Qb[r * 36 + k0u + tg];
                af[mt][1] = Qb[(r + 8) * 36 + k0u + tg];
                af[mt][2] = Qb[r * 36 + k0u + tg + 4];
                af[mt][3] = Qb[(r + 8) * 36 + k0u + tg + 4];
            }
            #pragma unroll
            for (int nt = 0; nt < 2; nt++) {
                int rr = kcol0 + nt * 8 + g;
                bf[nt][0] = Kb[rr * 36 + k0u + tg];
                bf[nt][1] = Kb[rr * 36 + k0u + tg + 4];
            }
            #pragma unroll
            for (int mt = 0; mt < 2; mt++)
                #pragma unroll
                for (int nt = 0; nt < 2; nt++)
                    mma16(acc[b][mt][nt], af[mt], bf[nt]);
        }
    }

    // register-local batch softmax + bf16 P write
    #pragma unroll
    for (int mt = 0; mt < 2; mt++) {
        int row_lo = qbase + qrow0 + mt * 16 + g;
        #pragma unroll
        for (int nt = 0; nt < 2; nt++) {
            int colu = (kbase + kcol0 + nt * 8) / 2 + tg;   // uint col index
            float p[4][4];   // [r][b]
            #pragma unroll
            for (int r = 0; r < 4; r++) {
                float s0 = acc[0][mt][nt][r] * 0.125f;
                float s1 = acc[1][mt][nt][r] * 0.125f;
                float s2 = acc[2][mt][nt][r] * 0.125f;
                float s3 = acc[3][mt][nt][r] * 0.125f;
                float m = fmaxf(fmaxf(s0, s1), fmaxf(s2, s3));
                float e0 = __expf(s0 - m), e1 = __expf(s1 - m);
                float e2 = __expf(s2 - m), e3 = __expf(s3 - m);
                float rv = 1.0f / (e0 + e1 + e2 + e3);
                p[r][0] = e0 * rv; p[r][1] = e1 * rv;
                p[r][2] = e2 * rv; p[r][3] = e3 * rv;
            }
            #pragma unroll
            for (int b = 0; b < 4; b++) {
                unsigned* Pb = g_P + (size_t)b * (PL / 2);
                Pb[(size_t)row_lo * (NK / 2) + colu]       = pack_bf16(p[0][b], p[1][b]);
                Pb[(size_t)(row_lo + 8) * (NK / 2) + colu] = pack_bf16(p[2][b], p[3][b]);
            }
        }
    }
}

// ============================================================================
// Kernel 4: O = P @ V (bf16 m16n8k16), split-K=4, cp.async double-buffered.
// BM=128, BN=128(c), BK=32. 8 warps (4m x 2n). grid (8, 2, 16).
// ============================================================================
#define PS_BUF (128 * 20)    // uints (rows: 16 data + 4 pad)
#define VS_BUF (128 * 20)
#define PV_SMEM_BYTES (2 * (PS_BUF + VS_BUF) * 4)   // 40960 B

__global__ __launch_bounds__(256, 2) void pv_mma() {
    extern __shared__ uint32_t sm[];
    uint32_t smem_base = (uint32_t)__cvta_generic_to_shared(sm);

    int b = blockIdx.z >> 2;
    int split = blockIdx.z & 3;
    int m0 = blockIdx.x * 128, n0 = blockIdx.y * 128;
    int tid = threadIdx.x;
    int wid = tid >> 5;
    int g = (tid >> 2) & 7, tg = tid & 3;
    int mbase = (wid >> 1) * 32;
    int nbase = (wid & 1) * 64;

    const unsigned* Pu = g_P  + (size_t)b * (PL / 2);
    const unsigned* Vu = g_vt + (size_t)b * CC * (NK / 2);

    auto prefetch = [&](int kb, int buf) {
        int kbu = kb / 2;
        #pragma unroll
        for (int j = 0; j < 2; j++) {
            int f = j * 256 + tid;
            int row = f >> 2, c4 = f & 3;
            {   // P tile [128 m][32 k]
                uint32_t dst = smem_base + (buf * PS_BUF + row * 20 + c4 * 4) * 4;
                cp_async16(dst, Pu + (size_t)(m0 + row) * (NK / 2) + kbu + c4 * 4);
            }
            {   // V^T tile [128 c][32 k]
                uint32_t dst = smem_base + (2 * PS_BUF + buf * VS_BUF + row * 20 + c4 * 4) * 4;
                cp_async16(dst, Vu + (size_t)(n0 + row) * (NK / 2) + kbu + c4 * 4);
            }
        }
    };

    float acc[2][8][4];
    #pragma unroll
    for (int i = 0; i < 2; i++)
        #pragma unroll
        for (int j = 0; j < 8; j++)
            #pragma unroll
            for (int r = 0; r < 4; r++) acc[i][j][r] = 0.0f;

    const int kstart = split * (NK / PVSPLIT);
    const int NIT = (NK / PVSPLIT) / 32;   // 64

    prefetch(kstart, 0);
    CP_COMMIT();

    for (int it = 0; it < NIT; it++) {
        int buf = it & 1;
        if (it + 1 < NIT) {
            prefetch(kstart + (it + 1) * 32, buf ^ 1);
            CP_COMMIT();
            cp_wait<1>();
        } else {
            cp_wait<0>();
        }
        __syncthreads();

        const uint32_t* Ps = sm + buf * PS_BUF;
        const uint32_t* Vs = sm + 2 * PS_BUF + buf * VS_BUF;

        #pragma unroll
        for (int ks = 0; ks < 2; ks++) {
            int k0u = ks * 8;
            unsigned af[2][4], bf[8][2];
            #pragma unroll
            for (int mt = 0; mt < 2; mt++) {
                int mr = mbase + mt * 16 + g;
                af[mt][0] = Ps[mr * 20 + k0u + tg];
                af[mt][1] = Ps[(mr + 8) * 20 + k0u + tg];
                af[mt][2] = Ps[mr * 20 + k0u + tg + 4];
                af[mt][3] = Ps[(mr + 8) * 20 + k0u + tg + 4];
            }
            #pragma unroll
            for (int nt = 0; nt < 8; nt++) {
                int vr = (nbase + nt * 8 + g) * 20;
                bf[nt][0] = Vs[vr + k0u + tg];
                bf[nt][1] = Vs[vr + k0u + tg + 4];
            }
            #pragma unroll
            for (int mt = 0; mt < 2; mt++)
                #pragma unroll
                for (int nt = 0; nt < 8; nt++)
                    mma16(acc[mt][nt], af[mt], bf[nt]);
        }
        __syncthreads();
    }

    float* part = g_part + (size_t)split * (BB * PP * CC);
    #pragma unroll
    for (int mt = 0; mt < 2; mt++) {
        int r0 = m0 + mbase + mt * 16 + g;
        #pragma unroll
        for (int nt = 0; nt < 8; nt++) {
            int col = n0 + nbase + nt * 8 + 2 * tg;
            *(float2*)&part[(size_t)((b << 10) + r0) * CC + col] =
                make_float2(acc[mt][nt][0], acc[mt][nt][1]);
            *(float2*)&part[(size_t)((b << 10) + r0 + 8) * CC + col] =
                make_float2(acc[mt][nt][2], acc[mt][nt][3]);
        }
    }
}

// ============================================================================
// Kernel 5: deterministic 4-way split-K reduction into d_out ([b][p][c])
// ============================================================================
__global__ void reduce4(float* __restrict__ out) {
    int i = blockIdx.x * blockDim.x + threadIdx.x;
    const float4* p = (const float4*)g_part;
    const int plane = BB * PP * CC / 4;
    float4 s = p[i];
    #pragma unroll
    for (int sp = 1; sp < PVSPLIT; sp++) {
        float4 t = p[(size_t)sp * plane + i];
        s.x += t.x; s.y += t.y; s.z += t.z; s.w += t.w;
    }
    ((float4*)out)[i] = s;
}

// ============================================================================
extern "C" void kernel_launch(void* const* d_in, const int* in_sizes, int n_in,
                              void* d_out, int out_size) {
    const float* zx  = (const float*)d_in[0];
    const float* zy  = (const float*)d_in[1];
    const float* Wq  = (const float*)d_in[2];
    const float* bq  = (const float*)d_in[3];
    const float* Wpx = (const float*)d_in[4];
    const float* bpx = (const float*)d_in[5];
    const float* Wk  = (const float*)d_in[6];
    const float* bk  = (const float*)d_in[7];
    const float* Wpy = (const float*)d_in[8];
    const float* bpy = (const float*)d_in[9];
    const float* Wv  = (const float*)d_in[10];
    const float* bv  = (const float*)d_in[11];
    float* out = (float*)d_out;

    cudaFuncSetAttribute(qk_softmax, cudaFuncAttributeMaxDynamicSharedMemorySize,
                         QK_SMEM_BYTES);
    cudaFuncSetAttribute(pv_mma, cudaFuncAttributeMaxDynamicSharedMemorySize,
                         PV_SMEM_BYTES);

    pe_proj_kernel<<<dim3(PP, 2), CC>>>(Wpx, bpx, Wpy, bpy);
    proj_mma<<<dim3(8, 1, 4),  256>>>(zx, Wq, bq, 64, 0);    // q
    proj_mma<<<dim3(8, 1, 32), 256>>>(zy, Wk, bk, 64, 1);    // k
    proj_mma<<<dim3(8, 4, 32), 256>>>(zy, Wv, bv, 256, 2);   // v (transposed out)
    qk_softmax<<<dim3(PP / 64, NK / 64), 256, QK_SMEM_BYTES>>>();
    pv_mma<<<dim3(8, 2, 16), 256, PV_SMEM_BYTES>>>();
    reduce4<<<(BB * PP * CC / 4) / 256, 256>>>(out);
}

// round 6
// speedup vs baseline: 1.6121x; 1.0589x over previous
#include <cuda_runtime.h>
#include <cuda_bf16.h>
#include <cstdint>

// Fixed shapes
#define BB 4
#define CC 256
#define PP 1024
#define NK 8192
#define AA 64
#define PL (PP * NK)
#define PVSPLIT 4

// -------- device scratch --------
__device__ unsigned g_q[BB * PP * AA / 2];            // 0.5 MB  [b][p][a/2] bf16x2
__device__ unsigned g_k[BB * NK * AA / 2];            //  4 MB   [b][k][a/2]
__device__ unsigned g_vt[BB * CC * NK / 2];           // 16 MB   [b][c][k/2]  (V^T)
__device__ unsigned g_P[(size_t)BB * PL / 2];         // 64 MB   [b][p][k/2]
__device__ float g_peq[PP * AA];
__device__ float g_pek[PP * AA];
__device__ float g_part[PVSPLIT * BB * PP * CC];      // 16 MB fp32 partials

// -------- helpers --------
__device__ __forceinline__ uint32_t f2tf(float f) {
    uint32_t r;
    asm("cvt.rna.tf32.f32 %0, %1;" : "=r"(r) : "f"(f));
    return r;
}
__device__ __forceinline__ unsigned pack_bf16(float lo, float hi) {
    unsigned r;
    asm("cvt.rn.bf16x2.f32 %0, %1, %2;" : "=r"(r) : "f"(hi), "f"(lo));
    return r;
}
__device__ __forceinline__ void mma8(float* c, const uint32_t* a, const uint32_t* b) {
    asm volatile("mma.sync.aligned.m16n8k8.row.col.f32.tf32.tf32.f32 "
                 "{%0,%1,%2,%3}, {%4,%5,%6,%7}, {%8,%9}, {%0,%1,%2,%3};"
                 : "+f"(c[0]), "+f"(c[1]), "+f"(c[2]), "+f"(c[3])
                 : "r"(a[0]), "r"(a[1]), "r"(a[2]), "r"(a[3]), "r"(b[0]), "r"(b[1]));
}
__device__ __forceinline__ void mma16(float* c, const unsigned* a, const unsigned* b) {
    asm volatile("mma.sync.aligned.m16n8k16.row.col.f32.bf16.bf16.f32 "
                 "{%0,%1,%2,%3}, {%4,%5,%6,%7}, {%8,%9}, {%0,%1,%2,%3};"
                 : "+f"(c[0]), "+f"(c[1]), "+f"(c[2]), "+f"(c[3])
                 : "r"(a[0]), "r"(a[1]), "r"(a[2]), "r"(a[3]), "r"(b[0]), "r"(b[1]));
}
__device__ __forceinline__ uint4 cvt4(float4 v) {
    uint4 r;
    r.x = f2tf(v.x); r.y = f2tf(v.y); r.z = f2tf(v.z); r.w = f2tf(v.w);
    return r;
}
__device__ __forceinline__ void cp_async16(uint32_t dst, const void* src) {
    asm volatile("cp.async.cg.shared.global [%0], [%1], 16;" :: "r"(dst), "l"(src));
}
#define CP_COMMIT() asm volatile("cp.async.commit_group;")
template<int N> __device__ __forceinline__ void cp_wait() {
    asm volatile("cp.async.wait_group %0;" :: "n"(N));
}

// ============================================================================
// Kernel 1: positional-encoding projections pe_q / pe_k  [1024, 64] (fp32)
// ============================================================================
__global__ void pe_proj_kernel(const float* __restrict__ Wpx, const float* __restrict__ bpx,
                               const float* __restrict__ Wpy, const float* __restrict__ bpy) {
    int p = blockIdx.x;
    int y = p >> 5, x = p & 31;
    const float* W = blockIdx.y ? Wpy : Wpx;
    const float* bb = blockIdx.y ? bpy : bpx;
    float* outp = blockIdx.y ? g_pek : g_peq;

    __shared__ float pe[CC];
    int c = threadIdx.x;
    {
        int pos = (c < 128) ? y : x;
        int idx = (c < 128) ? c : (c - 128);
        int j = idx >> 1;
        float ang = (float)pos * expf(-logf(10000.0f) * (float)j / 64.0f);
        pe[c] = (idx & 1) ? cosf(ang) : sinf(ang);
    }
    __syncthreads();
    if (c < AA) {
        float s = 0.0f;
        #pragma unroll 8
        for (int i = 0; i < CC; i++) s += pe[i] * W[c * CC + i];
        outp[p * AA + c] = s + bb[c];
    }
}

// ============================================================================
// Kernel 2: tf32 projection GEMM -> bf16 outputs, register-pipelined loads.
// mode 0: q -> g_q (+pe), mode 1: k -> g_k (+pe), mode 2: v -> g_vt TRANSPOSED
// ============================================================================
__global__ __launch_bounds__(256) void proj_mma(const float* __restrict__ A,
                                                const float* __restrict__ W,
                                                const float* __restrict__ bias,
                                                int N, int mode) {
    __shared__ uint32_t As[32][136];
    __shared__ uint32_t Ws[64][36];

    int z = blockIdx.z;
    A += (size_t)z * CC * PP;
    int m0 = blockIdx.x * 128, n0 = blockIdx.y * 64;

    int tid = threadIdx.x;
    int wid = tid >> 5;
    int g = (tid >> 2) & 7, tg = tid & 3;
    int mbase = (wid >> 1) * 32;
    int nbase = (wid & 1) * 32;

    // load-thread coordinates (fixed across iterations)
    const int arow = tid >> 3, ac4 = tid & 7;        // A: 2 rows per thread step of 16... (see below)
    const int wrow = tid >> 3, wc4 = tid & 7;

    float acc[2][4][4];
    #pragma unroll
    for (int i = 0; i < 2; i++)
        #pragma unroll
        for (int j = 0; j < 4; j++)
            #pragma unroll
            for (int r = 0; r < 4; r++) acc[i][j][r] = 0.0f;

    float4 ar[4], wr[2];
    auto ldA = [&](int c0) {
        #pragma unroll
        for (int i = 0; i < 4; i++) {
            int idx = i * 256 + tid;
            int row = idx >> 5, c4 = idx & 31;
            ar[i] = *(const float4*)&A[(size_t)(c0 + row) * PP + m0 + c4 * 4];
        }
    };
    auto ldW = [&](int c0) {
        #pragma unroll
        for (int i = 0; i < 2; i++) {
            int idx = i * 256 + tid;
            int row = idx >> 3, c4 = idx & 7;
            wr[i] = *(const float4*)&W[(size_t)(n0 + row) * CC + c0 + c4 * 4];
        }
    };

    ldA(0); ldW(0);

    for (int c0 = 0; c0 < CC; c0 += 32) {
        // store current regs to smem (with tf32 cvt)
        #pragma unroll
        for (int i = 0; i < 4; i++) {
            int idx = i * 256 + tid;
            int row = idx >> 5, c4 = idx & 31;
            *(uint4*)&As[row][c4 * 4] = cvt4(ar[i]);
        }
        #pragma unroll
        for (int i = 0; i < 2; i++) {
            int idx = i * 256 + tid;
            int row = idx >> 3, c4 = idx & 7;
            *(uint4*)&Ws[row][c4 * 4] = cvt4(wr[i]);
        }
        __syncthreads();

        if (c0 + 32 < CC) { ldA(c0 + 32); ldW(c0 + 32); }   // overlaps mma below

        #pragma unroll
        for (int ks = 0; ks < 4; ks++) {
            int k0 = ks * 8;
            uint32_t af[2][4], bf[4][2];
            #pragma unroll
            for (int mt = 0; mt < 2; mt++) {
                int mr = mbase + mt * 16;
                af[mt][0] = As[k0 + tg][mr + g];
                af[mt][1] = As[k0 + tg][mr + g + 8];
                af[mt][2] = As[k0 + tg + 4][mr + g];
                af[mt][3] = As[k0 + tg + 4][mr + g + 8];
            }
            #pragma unroll
            for (int nt = 0; nt < 4; nt++) {
                int nr = nbase + nt * 8;
                bf[nt][0] = Ws[nr + g][k0 + tg];
                bf[nt][1] = Ws[nr + g][k0 + tg + 4];
            }
            #pragma unroll
            for (int mt = 0; mt < 2; mt++)
                #pragma unroll
                for (int nt = 0; nt < 4; nt++)
                    mma8(acc[mt][nt], af[mt], bf[nt]);
        }
        __syncthreads();
    }

    if (mode < 2) {
        const float* extra = (mode == 0) ? g_peq : g_pek;
        unsigned* C = (mode == 0 ? g_q : g_k) + (size_t)z * PP * (N / 2);
        #pragma unroll
        for (int mt = 0; mt < 2; mt++) {
            int r0 = m0 + mbase + mt * 16 + g;
            #pragma unroll
            for (int nt = 0; nt < 4; nt++) {
                int col = n0 + nbase + nt * 8 + 2 * tg;
                float b0 = bias[col], b1 = bias[col + 1];
                float e00 = extra[r0 * AA + col],       e01 = extra[r0 * AA + col + 1];
                float e10 = extra[(r0 + 8) * AA + col], e11 = extra[(r0 + 8) * AA + col + 1];
                C[r0 * (N / 2) + col / 2] =
                    pack_bf16(acc[mt][nt][0] + b0 + e00, acc[mt][nt][1] + b1 + e01);
                C[(r0 + 8) * (N / 2) + col / 2] =
                    pack_bf16(acc[mt][nt][2] + b0 + e10, acc[mt][nt][3] + b1 + e11);
            }
        }
    } else {
        // v: stage bf16 transposed tile [64 n][128 m] in smem, write g_vt coalesced
        __nv_bfloat16* Cs = (__nv_bfloat16*)&As[0][0];   // 64 x 132 bf16 rows (66 uints)
        #pragma unroll
        for (int mt = 0; mt < 2; mt++) {
            int r0 = mbase + mt * 16 + g;
            #pragma unroll
            for (int nt = 0; nt < 4; nt++) {
                int col = nbase + nt * 8 + 2 * tg;
                float b0 = bias[n0 + col], b1 = bias[n0 + col + 1];
                Cs[(col)     * 132 + r0]     = __float2bfloat16(acc[mt][nt][0] + b0);
                Cs[(col + 1) * 132 + r0]     = __float2bfloat16(acc[mt][nt][1] + b1);
                Cs[(col)     * 132 + r0 + 8] = __float2bfloat16(acc[mt][nt][2] + b0);
                Cs[(col + 1) * 132 + r0 + 8] = __float2bfloat16(acc[mt][nt][3] + b1);
            }
        }
        __syncthreads();
        int b = z >> 3, page = z & 7;
        const unsigned* Csu = (const unsigned*)Cs;
        #pragma unroll
        for (int j = 0; j < 16; j++) {
            int f = j * 256 + tid;
            int n = f >> 6, u = f & 63;
            g_vt[(size_t)(b * CC + n0 + n) * (NK / 2) + page * 512 + m0 / 2 + u] =
                Csu[n * 66 + u];
        }
    }
}

// ============================================================================
// Kernel 3: QK^T (bf16) + register-local batch softmax -> P (bf16), with
// smem-staged COALESCED P writes (uint4).
// Block: 64q x 64k for all 4 batches. Grid (16, 128), 256 threads.
// ============================================================================
#define QK_TILE (4 * 64 * 36)                 // per tensor, uints
#define QK_SMEM_BYTES (2 * QK_TILE * 4)       // 73728 B

__global__ __launch_bounds__(256) void qk_softmax() {
    extern __shared__ uint32_t sm[];
    uint32_t* Qs = sm;             // [4][64][36]
    uint32_t* Ks = sm + QK_TILE;

    const int tid = threadIdx.x;
    const int wid = tid >> 5;
    const int g = (tid >> 2) & 7, tg = tid & 3;
    const int qbase = blockIdx.x * 64, kbase = blockIdx.y * 64;

    #pragma unroll
    for (int j = 0; j < 8; j++) {
        int f = j * 256 + tid;
        int row = f >> 3, a4 = f & 7;
        int b = row >> 6, r = row & 63;
        *(uint4*)&Qs[row * 36 + a4 * 4] =
            *(const uint4*)&g_q[((b << 10) + qbase + r) * 32 + a4 * 4];
        *(uint4*)&Ks[row * 36 + a4 * 4] =
            *(const uint4*)&g_k[((b << 13) + kbase + r) * 32 + a4 * 4];
    }
    __syncthreads();

    const int wm = wid >> 2, wn = wid & 3;
    const int qrow0 = wm * 32, kcol0 = wn * 16;

    float acc[4][2][2][4];
    #pragma unroll
    for (int b = 0; b < 4; b++)
        #pragma unroll
        for (int i = 0; i < 2; i++)
            #pragma unroll
            for (int j = 0; j < 2; j++)
                #pragma unroll
                for (int r = 0; r < 4; r++) acc[b][i][j][r] = 0.0f;

    #pragma unroll
    for (int ks = 0; ks < 4; ks++) {
        int k0u = ks * 8;
        #pragma unroll
        for (int b = 0; b < 4; b++) {
            const uint32_t* Qb = Qs + b * 64 * 36;
            const uint32_t* Kb = Ks + b * 64 * 36;
            unsigned af[2][4], bf[2][2];
            #pragma unroll
            for (int mt = 0; mt < 2; mt++) {
                int r = qrow0 + mt * 16 + g;
                af[mt][0] = Qb[r * 36 + k0u + tg];
                af[mt][1] = Qb[(r + 8) * 36 + k0u + tg];
                af[mt][2] = Qb[r * 36 + k0u + tg + 4];
                af[mt][3] = Qb[(r + 8) * 36 + k0u + tg + 4];
            }
            #pragma unroll
            for (int nt = 0; nt < 2; nt++) {
                int rr = kcol0 + nt * 8 + g;
                bf[nt][0] = Kb[rr * 36 + k0u + tg];
                bf[nt][1] = Kb[rr * 36 + k0u + tg + 4];
            }
            #pragma unroll
            for (int mt = 0; mt < 2; mt++)
                #pragma unroll
                for (int nt = 0; nt < 2; nt++)
                    mma16(acc[b][mt][nt], af[mt], bf[nt]);
        }
    }

    // all reads of Qs/Ks are done -> reuse Qs region to stage P: [4 b][64 q][36]
    __syncthreads();
    uint32_t* Ps = sm;

    #pragma unroll
    for (int mt = 0; mt < 2; mt++) {
        int lo = qrow0 + mt * 16 + g;           // local q row
        #pragma unroll
        for (int nt = 0; nt < 2; nt++) {
            int cu = kcol0 / 2 + nt * 4 + tg;   // local uint col (0..31)
            float p[4][4];   // [r][b]
            #pragma unroll
            for (int r = 0; r < 4; r++) {
                float s0 = acc[0][mt][nt][r] * 0.125f;
                float s1 = acc[1][mt][nt][r] * 0.125f;
                float s2 = acc[2][mt][nt][r] * 0.125f;
                float s3 = acc[3][mt][nt][r] * 0.125f;
                float m = fmaxf(fmaxf(s0, s1), fmaxf(s2, s3));
                float e0 = __expf(s0 - m), e1 = __expf(s1 - m);
                float e2 = __expf(s2 - m), e3 = __expf(s3 - m);
                float rv = 1.0f / (e0 + e1 + e2 + e3);
                p[r][0] = e0 * rv; p[r][1] = e1 * rv;
                p[r][2] = e2 * rv; p[r][3] = e3 * rv;
            }
            #pragma unroll
            for (int b = 0; b < 4; b++) {
                Ps[b * 2304 + lo * 36 + cu]       = pack_bf16(p[0][b], p[1][b]);
                Ps[b * 2304 + (lo + 8) * 36 + cu] = pack_bf16(p[2][b], p[3][b]);
            }
        }
    }
    __syncthreads();

    // coalesced copy-out: 4b x 64 rows x 8 uint4
    #pragma unroll
    for (int j = 0; j < 8; j++) {
        int f = j * 256 + tid;
        int b = f >> 9, r = (f >> 3) & 63, q4 = f & 7;
        uint4 val = *(const uint4*)&Ps[b * 2304 + r * 36 + q4 * 4];
        *(uint4*)&g_P[(size_t)b * (PL / 2) + (size_t)(qbase + r) * (NK / 2) + kbase / 2 + q4 * 4] = val;
    }
}

// ============================================================================
// Kernel 4: O = P @ V (bf16), split-K=4, 3-stage cp.async pipeline.
// BM=128, BN=128(c), BK=32. 8 warps (4m x 2n). grid (8, 2, 16).
// ============================================================================
#define PS_BUF (128 * 20)    // uints per stage
#define VS_BUF (128 * 20)
#define STAGE  (PS_BUF + VS_BUF)
#define PV_SMEM_BYTES (3 * STAGE * 4)   // 61440 B

__global__ __launch_bounds__(256, 2) void pv_mma() {
    extern __shared__ uint32_t sm[];
    uint32_t smem_base = (uint32_t)__cvta_generic_to_shared(sm);

    int b = blockIdx.z >> 2;
    int split = blockIdx.z & 3;
    int m0 = blockIdx.x * 128, n0 = blockIdx.y * 128;
    int tid = threadIdx.x;
    int wid = tid >> 5;
    int g = (tid >> 2) & 7, tg = tid & 3;
    int mbase = (wid >> 1) * 32;
    int nbase = (wid & 1) * 64;

    const unsigned* Pu = g_P  + (size_t)b * (PL / 2);
    const unsigned* Vu = g_vt + (size_t)b * CC * (NK / 2);

    const int kstart = split * (NK / PVSPLIT);
    const int NIT = (NK / PVSPLIT) / 32;   // 64

    auto prefetch = [&](int it, int stage) {
        int kbu = (kstart + it * 32) / 2;
        #pragma unroll
        for (int j = 0; j < 2; j++) {
            int f = j * 256 + tid;
            int row = f >> 2, c4 = f & 3;
            uint32_t dst = smem_base + (stage * STAGE + row * 20 + c4 * 4) * 4;
            cp_async16(dst, Pu + (size_t)(m0 + row) * (NK / 2) + kbu + c4 * 4);
            uint32_t dst2 = smem_base + (stage * STAGE + PS_BUF + row * 20 + c4 * 4) * 4;
            cp_async16(dst2, Vu + (size_t)(n0 + row) * (NK / 2) + kbu + c4 * 4);
        }
        CP_COMMIT();
    };

    float acc[2][8][4];
    #pragma unroll
    for (int i = 0; i < 2; i++)
        #pragma unroll
        for (int j = 0; j < 8; j++)
            #pragma unroll
            for (int r = 0; r < 4; r++) acc[i][j][r] = 0.0f;

    prefetch(0, 0);
    prefetch(1, 1);

    for (int it = 0; it < NIT; it++) {
        int stage = it % 3;
        if (it + 2 < NIT) {
            prefetch(it + 2, (it + 2) % 3);
            cp_wait<2>();
        } else if (it + 1 < NIT) {
            cp_wait<1>();
        } else {
            cp_wait<0>();
        }
        __syncthreads();

        const uint32_t* Ps = sm + stage * STAGE;
        const uint32_t* Vs = Ps + PS_BUF;

        #pragma unroll
        for (int ks = 0; ks < 2; ks++) {
            int k0u = ks * 8;
            unsigned af[2][4], bf[8][2];
            #pragma unroll
            for (int mt = 0; mt < 2; mt++) {
                int mr = mbase + mt * 16 + g;
                af[mt][0] = Ps[mr * 20 + k0u + tg];
                af[mt][1] = Ps[(mr + 8) * 20 + k0u + tg];
                af[mt][2] = Ps[mr * 20 + k0u + tg + 4];
                af[mt][3] = Ps[(mr + 8) * 20 + k0u + tg + 4];
            }
            #pragma unroll
            for (int nt = 0; nt < 8; nt++) {
                int vr = (nbase + nt * 8 + g) * 20;
                bf[nt][0] = Vs[vr + k0u + tg];
                bf[nt][1] = Vs[vr + k0u + tg + 4];
            }
            #pragma unroll
            for (int mt = 0; mt < 2; mt++)
                #pragma unroll
                for (int nt = 0; nt < 8; nt++)
                    mma16(acc[mt][nt], af[mt], bf[nt]);
        }
        __syncthreads();
    }

    float* part = g_part + (size_t)split * (BB * PP * CC);
    #pragma unroll
    for (int mt = 0; mt < 2; mt++) {
        int r0 = m0 + mbase + mt * 16 + g;
        #pragma unroll
        for (int nt = 0; nt < 8; nt++) {
            int col = n0 + nbase + nt * 8 + 2 * tg;
            *(float2*)&part[(size_t)((b << 10) + r0) * CC + col] =
                make_float2(acc[mt][nt][0], acc[mt][nt][1]);
            *(float2*)&part[(size_t)((b << 10) + r0 + 8) * CC + col] =
                make_float2(acc[mt][nt][2], acc[mt][nt][3]);
        }
    }
}

// ============================================================================
// Kernel 5: deterministic 4-way split-K reduction into d_out ([b][p][c])
// ============================================================================
__global__ void reduce4(float* __restrict__ out) {
    int i = blockIdx.x * blockDim.x + threadIdx.x;
    const float4* p = (const float4*)g_part;
    const int plane = BB * PP * CC / 4;
    float4 s = p[i];
    #pragma unroll
    for (int sp = 1; sp < PVSPLIT; sp++) {
        float4 t = p[(size_t)sp * plane + i];
        s.x += t.x; s.y += t.y; s.z += t.z; s.w += t.w;
    }
    ((float4*)out)[i] = s;
}

// ============================================================================
extern "C" void kernel_launch(void* const* d_in, const int* in_sizes, int n_in,
                              void* d_out, int out_size) {
    const float* zx  = (const float*)d_in[0];
    const float* zy  = (const float*)d_in[1];
    const float* Wq  = (const float*)d_in[2];
    const float* bq  = (const float*)d_in[3];
    const float* Wpx = (const float*)d_in[4];
    const float* bpx = (const float*)d_in[5];
    const float* Wk  = (const float*)d_in[6];
    const float* bk  = (const float*)d_in[7];
    const float* Wpy = (const float*)d_in[8];
    const float* bpy = (const float*)d_in[9];
    const float* Wv  = (const float*)d_in[10];
    const float* bv  = (const float*)d_in[11];
    float* out = (float*)d_out;

    cudaFuncSetAttribute(qk_softmax, cudaFuncAttributeMaxDynamicSharedMemorySize,
                         QK_SMEM_BYTES);
    cudaFuncSetAttribute(pv_mma, cudaFuncAttributeMaxDynamicSharedMemorySize,
                         PV_SMEM_BYTES);

    pe_proj_kernel<<<dim3(PP, 2), CC>>>(Wpx, bpx, Wpy, bpy);
    proj_mma<<<dim3(8, 1, 4),  256>>>(zx, Wq, bq, 64, 0);    // q
    proj_mma<<<dim3(8, 1, 32), 256>>>(zy, Wk, bk, 64, 1);    // k
    proj_mma<<<dim3(8, 4, 32), 256>>>(zy, Wv, bv, 256, 2);   // v (transposed out)
    qk_softmax<<<dim3(PP / 64, NK / 64), 256, QK_SMEM_BYTES>>>();
    pv_mma<<<dim3(8, 2, 16), 256, PV_SMEM_BYTES>>>();
    reduce4<<<(BB * PP * CC / 4) / 256, 256>>>(out);
}

// round 8
// speedup vs baseline: 1.6491x; 1.0230x over previous
#include <cuda_runtime.h>
#include <cuda_bf16.h>
#include <cstdint>

// Fixed shapes
#define BB 4
#define CC 256
#define PP 1024
#define NK 8192
#define AA 64
#define PL (PP * NK)
#define PVSPLIT 4

// -------- device scratch --------
__device__ unsigned g_q[BB * PP * AA / 2];            // 0.5 MB  [b][p][a/2] bf16x2
__device__ unsigned g_k[BB * NK * AA / 2];            //  4 MB   [b][k][a/2]
__device__ unsigned g_vt[BB * CC * NK / 2];           // 16 MB   [b][c][k/2]  (V^T)
__device__ unsigned g_P[(size_t)BB * PL / 2];         // 64 MB   [b][p][k/2]
__device__ float g_peq[PP * AA];
__device__ float g_pek[PP * AA];
__device__ float g_part[PVSPLIT * BB * PP * CC];      // 16 MB fp32 partials

// -------- helpers --------
__device__ __forceinline__ uint32_t f2tf(float f) {
    uint32_t r;
    asm("cvt.rna.tf32.f32 %0, %1;" : "=r"(r) : "f"(f));
    return r;
}
__device__ __forceinline__ unsigned pack_bf16(float lo, float hi) {
    unsigned r;
    asm("cvt.rn.bf16x2.f32 %0, %1, %2;" : "=r"(r) : "f"(hi), "f"(lo));
    return r;
}
__device__ __forceinline__ void mma8(float* c, const uint32_t* a, const uint32_t* b) {
    asm volatile("mma.sync.aligned.m16n8k8.row.col.f32.tf32.tf32.f32 "
                 "{%0,%1,%2,%3}, {%4,%5,%6,%7}, {%8,%9}, {%0,%1,%2,%3};"
                 : "+f"(c[0]), "+f"(c[1]), "+f"(c[2]), "+f"(c[3])
                 : "r"(a[0]), "r"(a[1]), "r"(a[2]), "r"(a[3]), "r"(b[0]), "r"(b[1]));
}
__device__ __forceinline__ void mma16(float* c, const unsigned* a, const unsigned* b) {
    asm volatile("mma.sync.aligned.m16n8k16.row.col.f32.bf16.bf16.f32 "
                 "{%0,%1,%2,%3}, {%4,%5,%6,%7}, {%8,%9}, {%0,%1,%2,%3};"
                 : "+f"(c[0]), "+f"(c[1]), "+f"(c[2]), "+f"(c[3])
                 : "r"(a[0]), "r"(a[1]), "r"(a[2]), "r"(a[3]), "r"(b[0]), "r"(b[1]));
}
// ldmatrix x4: r0..r3 <- four 8x8 b16 tiles, addresses from lanes 0-7/8-15/16-23/24-31
__device__ __forceinline__ void ldm_x4(unsigned* r, uint32_t addr) {
    asm volatile("ldmatrix.sync.aligned.m8n8.x4.shared.b16 {%0,%1,%2,%3}, [%4];"
                 : "=r"(r[0]), "=r"(r[1]), "=r"(r[2]), "=r"(r[3]) : "r"(addr));
}
__device__ __forceinline__ uint4 cvt4(float4 v) {
    uint4 r;
    r.x = f2tf(v.x); r.y = f2tf(v.y); r.z = f2tf(v.z); r.w = f2tf(v.w);
    return r;
}
__device__ __forceinline__ void cp_async16(uint32_t dst, const void* src) {
    asm volatile("cp.async.cg.shared.global [%0], [%1], 16;" :: "r"(dst), "l"(src));
}
#define CP_COMMIT() asm volatile("cp.async.commit_group;")
template<int N> __device__ __forceinline__ void cp_wait() {
    asm volatile("cp.async.wait_group %0;" :: "n"(N));
}
__device__ __forceinline__ uint32_t smem_u32(const void* p) {
    return (uint32_t)__cvta_generic_to_shared(p);
}

// Lane-offset builders for ldmatrix address patterns (row stride 36 uints).
// A-pattern: r0=(m0-7,k0) r1=(m8-15,k0) r2=(m0-7,k+8bf16) r3=(m8-15,k+8)
__device__ __forceinline__ int laneA_off(int L) {
    return ((((L >> 3) & 1) * 8 + (L & 7)) * 36 + (L >> 4) * 4) * 4;
}
// B-pattern: r0=(n0-7,k0) r1=(n0-7,k8) r2=(n8-15,k0) r3=(n8-15,k8)
__device__ __forceinline__ int laneB_off(int L) {
    return (((L >> 4) * 8 + (L & 7)) * 36 + ((L >> 3) & 1) * 4) * 4;
}

// ============================================================================
// Kernel 1: positional-encoding projections pe_q / pe_k  [1024, 64] (fp32)
// ============================================================================
__global__ void pe_proj_kernel(const float* __restrict__ Wpx, const float* __restrict__ bpx,
                               const float* __restrict__ Wpy, const float* __restrict__ bpy) {
    int p = blockIdx.x;
    int y = p >> 5, x = p & 31;
    const float* W = blockIdx.y ? Wpy : Wpx;
    const float* bb = blockIdx.y ? bpy : bpx;
    float* outp = blockIdx.y ? g_pek : g_peq;

    __shared__ float pe[CC];
    int c = threadIdx.x;
    {
        int pos = (c < 128) ? y : x;
        int idx = (c < 128) ? c : (c - 128);
        int j = idx >> 1;
        float ang = (float)pos * expf(-logf(10000.0f) * (float)j / 64.0f);
        pe[c] = (idx & 1) ? cosf(ang) : sinf(ang);
    }
    __syncthreads();
    if (c < AA) {
        float s = 0.0f;
        #pragma unroll 8
        for (int i = 0; i < CC; i++) s += pe[i] * W[c * CC + i];
        outp[p * AA + c] = s + bb[c];
    }
}

// ============================================================================
// Kernel 2: tf32 projection GEMM -> bf16 outputs, register-pipelined loads.
// (unchanged from R6)
// ============================================================================
__global__ __launch_bounds__(256) void proj_mma(const float* __restrict__ A,
                                                const float* __restrict__ W,
                                                const float* __restrict__ bias,
                                                int N, int mode) {
    __shared__ uint32_t As[32][136];
    __shared__ uint32_t Ws[64][36];

    int z = blockIdx.z;
    A += (size_t)z * CC * PP;
    int m0 = blockIdx.x * 128, n0 = blockIdx.y * 64;

    int tid = threadIdx.x;
    int wid = tid >> 5;
    int g = (tid >> 2) & 7, tg = tid & 3;
    int mbase = (wid >> 1) * 32;
    int nbase = (wid & 1) * 32;

    float acc[2][4][4];
    #pragma unroll
    for (int i = 0; i < 2; i++)
        #pragma unroll
        for (int j = 0; j < 4; j++)
            #pragma unroll
            for (int r = 0; r < 4; r++) acc[i][j][r] = 0.0f;

    float4 ar[4], wr[2];
    auto ldA = [&](int c0) {
        #pragma unroll
        for (int i = 0; i < 4; i++) {
            int idx = i * 256 + tid;
            int row = idx >> 5, c4 = idx & 31;
            ar[i] = *(const float4*)&A[(size_t)(c0 + row) * PP + m0 + c4 * 4];
        }
    };
    auto ldW = [&](int c0) {
        #pragma unroll
        for (int i = 0; i < 2; i++) {
            int idx = i * 256 + tid;
            int row = idx >> 3, c4 = idx & 7;
            wr[i] = *(const float4*)&W[(size_t)(n0 + row) * CC + c0 + c4 * 4];
        }
    };

    ldA(0); ldW(0);

    for (int c0 = 0; c0 < CC; c0 += 32) {
        #pragma unroll
        for (int i = 0; i < 4; i++) {
            int idx = i * 256 + tid;
            int row = idx >> 5, c4 = idx & 31;
            *(uint4*)&As[row][c4 * 4] = cvt4(ar[i]);
        }
        #pragma unroll
        for (int i = 0; i < 2; i++) {
            int idx = i * 256 + tid;
            int row = idx >> 3, c4 = idx & 7;
            *(uint4*)&Ws[row][c4 * 4] = cvt4(wr[i]);
        }
        __syncthreads();

        if (c0 + 32 < CC) { ldA(c0 + 32); ldW(c0 + 32); }

        #pragma unroll
        for (int ks = 0; ks < 4; ks++) {
            int k0 = ks * 8;
            uint32_t af[2][4], bf[4][2];
            #pragma unroll
            for (int mt = 0; mt < 2; mt++) {
                int mr = mbase + mt * 16;
                af[mt][0] = As[k0 + tg][mr + g];
                af[mt][1] = As[k0 + tg][mr + g + 8];
                af[mt][2] = As[k0 + tg + 4][mr + g];
                af[mt][3] = As[k0 + tg + 4][mr + g + 8];
            }
            #pragma unroll
            for (int nt = 0; nt < 4; nt++) {
                int nr = nbase + nt * 8;
                bf[nt][0] = Ws[nr + g][k0 + tg];
                bf[nt][1] = Ws[nr + g][k0 + tg + 4];
            }
            #pragma unroll
            for (int mt = 0; mt < 2; mt++)
                #pragma unroll
                for (int nt = 0; nt < 4; nt++)
                    mma8(acc[mt][nt], af[mt], bf[nt]);
        }
        __syncthreads();
    }

    if (mode < 2) {
        const float* extra = (mode == 0) ? g_peq : g_pek;
        unsigned* C = (mode == 0 ? g_q : g_k) + (size_t)z * PP * (N / 2);
        #pragma unroll
        for (int mt = 0; mt < 2; mt++) {
            int r0 = m0 + mbase + mt * 16 + g;
            #pragma unroll
            for (int nt = 0; nt < 4; nt++) {
                int col = n0 + nbase + nt * 8 + 2 * tg;
                float b0 = bias[col], b1 = bias[col + 1];
                float e00 = extra[r0 * AA + col],       e01 = extra[r0 * AA + col + 1];
                float e10 = extra[(r0 + 8) * AA + col], e11 = extra[(r0 + 8) * AA + col + 1];
                C[r0 * (N / 2) + col / 2] =
                    pack_bf16(acc[mt][nt][0] + b0 + e00, acc[mt][nt][1] + b1 + e01);
                C[(r0 + 8) * (N / 2) + col / 2] =
                    pack_bf16(acc[mt][nt][2] + b0 + e10, acc[mt][nt][3] + b1 + e11);
            }
        }
    } else {
        __nv_bfloat16* Cs = (__nv_bfloat16*)&As[0][0];   // 64 x 132 bf16 rows
        #pragma unroll
        for (int mt = 0; mt < 2; mt++) {
            int r0 = mbase + mt * 16 + g;
            #pragma unroll
            for (int nt = 0; nt < 4; nt++) {
                int col = nbase + nt * 8 + 2 * tg;
                float b0 = bias[n0 + col], b1 = bias[n0 + col + 1];
                Cs[(col)     * 132 + r0]     = __float2bfloat16(acc[mt][nt][0] + b0);
                Cs[(col + 1) * 132 + r0]     = __float2bfloat16(acc[mt][nt][1] + b1);
                Cs[(col)     * 132 + r0 + 8] = __float2bfloat16(acc[mt][nt][2] + b0);
                Cs[(col + 1) * 132 + r0 + 8] = __float2bfloat16(acc[mt][nt][3] + b1);
            }
        }
        __syncthreads();
        int b = z >> 3, page = z & 7;
        const unsigned* Csu = (const unsigned*)Cs;
        #pragma unroll
        for (int j = 0; j < 16; j++) {
            int f = j * 256 + tid;
            int n = f >> 6, u = f & 63;
            g_vt[(size_t)(b * CC + n0 + n) * (NK / 2) + page * 512 + m0 / 2 + u] =
                Csu[n * 66 + u];
        }
    }
}

// ============================================================================
// Kernel 3: QK^T (bf16, ldmatrix feeds) + register-local batch softmax -> P.
// Block: 64q x 64k for all 4 batches. Grid (16, 128), 256 threads.
// ============================================================================
#define QK_TILE (4 * 64 * 36)
#define QK_SMEM_BYTES (2 * QK_TILE * 4)

__global__ __launch_bounds__(256) void qk_softmax() {
    extern __shared__ uint32_t sm[];
    uint32_t* Qs = sm;
    uint32_t* Ks = sm + QK_TILE;
    const uint32_t sb = smem_u32(sm);

    const int tid = threadIdx.x;
    const int wid = tid >> 5;
    const int L = tid & 31;
    const int g = (tid >> 2) & 7, tg = tid & 3;
    const int qbase = blockIdx.x * 64, kbase = blockIdx.y * 64;

    #pragma unroll
    for (int j = 0; j < 8; j++) {
        int f = j * 256 + tid;
        int row = f >> 3, a4 = f & 7;
        int b = row >> 6, r = row & 63;
        *(uint4*)&Qs[row * 36 + a4 * 4] =
            *(const uint4*)&g_q[((b << 10) + qbase + r) * 32 + a4 * 4];
        *(uint4*)&Ks[row * 36 + a4 * 4] =
            *(const uint4*)&g_k[((b << 13) + kbase + r) * 32 + a4 * 4];
    }
    __syncthreads();

    const int wm = wid >> 2, wn = wid & 3;
    const int qrow0 = wm * 32, kcol0 = wn * 16;

    const int aoff = laneA_off(L);
    const int boff = laneB_off(L);
    const uint32_t qa_base = sb + qrow0 * 36 * 4 + aoff;              // + b*2304*4 + mt*16*36*4 + k0u*4
    const uint32_t kb_base = sb + QK_TILE * 4 + kcol0 * 36 * 4 + boff;

    float acc[4][2][2][4];
    #pragma unroll
    for (int b = 0; b < 4; b++)
        #pragma unroll
        for (int i = 0; i < 2; i++)
            #pragma unroll
            for (int j = 0; j < 2; j++)
                #pragma unroll
                for (int r = 0; r < 4; r++) acc[b][i][j][r] = 0.0f;

    #pragma unroll
    for (int ks = 0; ks < 4; ks++) {
        int k0b = ks * 32;                      // byte offset of k16 step (8 uints)
        #pragma unroll
        for (int b = 0; b < 4; b++) {
            unsigned af[2][4], bf[4];
            ldm_x4(af[0], qa_base + b * 9216 + k0b);
            ldm_x4(af[1], qa_base + b * 9216 + 16 * 36 * 4 + k0b);
            ldm_x4(bf,    kb_base + b * 9216 + k0b);
            #pragma unroll
            for (int mt = 0; mt < 2; mt++)
                #pragma unroll
                for (int nt = 0; nt < 2; nt++)
                    mma16(acc[b][mt][nt], af[mt], bf + nt * 2);
        }
    }

    __syncthreads();
    uint32_t* Ps = sm;

    #pragma unroll
    for (int mt = 0; mt < 2; mt++) {
        int lo = qrow0 + mt * 16 + g;
        #pragma unroll
        for (int nt = 0; nt < 2; nt++) {
            int cu = kcol0 / 2 + nt * 4 + tg;
            float p[4][4];
            #pragma unroll
            for (int r = 0; r < 4; r++) {
                float s0 = acc[0][mt][nt][r] * 0.125f;
                float s1 = acc[1][mt][nt][r] * 0.125f;
                float s2 = acc[2][mt][nt][r] * 0.125f;
                float s3 = acc[3][mt][nt][r] * 0.125f;
                float m = fmaxf(fmaxf(s0, s1), fmaxf(s2, s3));
                float e0 = __expf(s0 - m), e1 = __expf(s1 - m);
                float e2 = __expf(s2 - m), e3 = __expf(s3 - m);
                float rv = 1.0f / (e0 + e1 + e2 + e3);
                p[r][0] = e0 * rv; p[r][1] = e1 * rv;
                p[r][2] = e2 * rv; p[r][3] = e3 * rv;
            }
            #pragma unroll
            for (int b = 0; b < 4; b++) {
                Ps[b * 2304 + lo * 36 + cu]       = pack_bf16(p[0][b], p[1][b]);
                Ps[b * 2304 + (lo + 8) * 36 + cu] = pack_bf16(p[2][b], p[3][b]);
            }
        }
    }
    __syncthreads();

    #pragma unroll
    for (int j = 0; j < 8; j++) {
        int f = j * 256 + tid;
        int b = f >> 9, r = (f >> 3) & 63, q4 = f & 7;
        uint4 val = *(const uint4*)&Ps[b * 2304 + r * 36 + q4 * 4];
        *(uint4*)&g_P[(size_t)b * (PL / 2) + (size_t)(qbase + r) * (NK / 2) + kbase / 2 + q4 * 4] = val;
    }
}

// ============================================================================
// Kernel 4: O = P @ V (bf16, ldmatrix feeds), split-K=4, BK=64 double-buffer.
// BM=128, BN=128(c). 8 warps (4m x 2n). grid (8, 2, 16).
// ============================================================================
#define PS_BUF (128 * 36)    // uints per stage (32 data + 4 pad per row)
#define VS_BUF (128 * 36)
#define STAGE  (PS_BUF + VS_BUF)
#define PV_SMEM_BYTES (2 * STAGE * 4)   // 73728 B

__global__ __launch_bounds__(256) void pv_mma() {
    extern __shared__ uint32_t sm[];
    const uint32_t sb = smem_u32(sm);

    int b = blockIdx.z >> 2;
    int split = blockIdx.z & 3;
    int m0 = blockIdx.x * 128, n0 = blockIdx.y * 128;
    int tid = threadIdx.x;
    int wid = tid >> 5;
    const int L = tid & 31;
    int g = (tid >> 2) & 7, tg = tid & 3;
    int mbase = (wid >> 1) * 32;
    int nbase = (wid & 1) * 64;

    const unsigned* Pu = g_P  + (size_t)b * (PL / 2);
    const unsigned* Vu = g_vt + (size_t)b * CC * (NK / 2);

    const int kstart = split * (NK / PVSPLIT);
    const int NIT = (NK / PVSPLIT) / 64;   // 32

    auto prefetch = [&](int it, int buf) {
        int kbu = (kstart + it * 64) / 2;
        #pragma unroll
        for (int j = 0; j < 4; j++) {
            int f = j * 256 + tid;
            int row = f >> 3, c4 = f & 7;
            uint32_t dst = sb + (buf * STAGE + row * 36 + c4 * 4) * 4;
            cp_async16(dst, Pu + (size_t)(m0 + row) * (NK / 2) + kbu + c4 * 4);
            uint32_t dst2 = sb + (buf * STAGE + PS_BUF + row * 36 + c4 * 4) * 4;
            cp_async16(dst2, Vu + (size_t)(n0 + row) * (NK / 2) + kbu + c4 * 4);
        }
        CP_COMMIT();
    };

    float acc[2][8][4];
    #pragma unroll
    for (int i = 0; i < 2; i++)
        #pragma unroll
        for (int j = 0; j < 8; j++)
            #pragma unroll
            for (int r = 0; r < 4; r++) acc[i][j][r] = 0.0f;

    const int aoff = laneA_off(L);
    const int boff = laneB_off(L);
    const uint32_t pa_base = sb + mbase * 36 * 4 + aoff;               // + stage + mt*16*36*4 + k0b
    const uint32_t vb_base = sb + PS_BUF * 4 + nbase * 36 * 4 + boff;  // + stage + j*16*36*4 + k0b

    prefetch(0, 0);
    prefetch(1, 1);

    for (int it = 0; it < NIT; it++) {
        int buf = it & 1;
        if (it + 1 < NIT) cp_wait<1>(); else cp_wait<0>();
        __syncthreads();

        uint32_t stg = (uint32_t)(buf * STAGE * 4);
        #pragma unroll
        for (int ks = 0; ks < 4; ks++) {
            int k0b = ks * 32;
            unsigned af[2][4], bf[4][4];
            ldm_x4(af[0], pa_base + stg + k0b);
            ldm_x4(af[1], pa_base + stg + 16 * 36 * 4 + k0b);
            #pragma unroll
            for (int j = 0; j < 4; j++)
                ldm_x4(bf[j], vb_base + stg + j * 16 * 36 * 4 + k0b);
            #pragma unroll
            for (int mt = 0; mt < 2; mt++)
                #pragma unroll
                for (int nt = 0; nt < 8; nt++)
                    mma16(acc[mt][nt], af[mt], bf[nt >> 1] + (nt & 1) * 2);
        }
        __syncthreads();
        if (it + 2 < NIT) prefetch(it + 2, buf);
    }

    float* part = g_part + (size_t)split * (BB * PP * CC);
    #pragma unroll
    for (int mt = 0; mt < 2; mt++) {
        int r0 = m0 + mbase + mt * 16 + g;
        #pragma unroll
        for (int nt = 0; nt < 8; nt++) {
            int col = n0 + nbase + nt * 8 + 2 * tg;
            *(float2*)&part[(size_t)((b << 10) + r0) * CC + col] =
                make_float2(acc[mt][nt][0], acc[mt][nt][1]);
            *(float2*)&part[(size_t)((b << 10) + r0 + 8) * CC + col] =
                make_float2(acc[mt][nt][2], acc[mt][nt][3]);
        }
    }
}

// ============================================================================
// Kernel 5: deterministic 4-way split-K reduction into d_out ([b][p][c])
// ============================================================================
__global__ void reduce4(float* __restrict__ out) {
    int i = blockIdx.x * blockDim.x + threadIdx.x;
    const float4* p = (const float4*)g_part;
    const int plane = BB * PP * CC / 4;
    float4 s = p[i];
    #pragma unroll
    for (int sp = 1; sp < PVSPLIT; sp++) {
        float4 t = p[(size_t)sp * plane + i];
        s.x += t.x; s.y += t.y; s.z += t.z; s.w += t.w;
    }
    ((float4*)out)[i] = s;
}

// ============================================================================
extern "C" void kernel_launch(void* const* d_in, const int* in_sizes, int n_in,
                              void* d_out, int out_size) {
    const float* zx  = (const float*)d_in[0];
    const float* zy  = (const float*)d_in[1];
    const float* Wq  = (const float*)d_in[2];
    const float* bq  = (const float*)d_in[3];
    const float* Wpx = (const float*)d_in[4];
    const float* bpx = (const float*)d_in[5];
    const float* Wk  = (const float*)d_in[6];
    const float* bk  = (const float*)d_in[7];
    const float* Wpy = (const float*)d_in[8];
    const float* bpy = (const float*)d_in[9];
    const float* Wv  = (const float*)d_in[10];
    const float* bv  = (const float*)d_in[11];
    float* out = (float*)d_out;

    cudaFuncSetAttribute(qk_softmax, cudaFuncAttributeMaxDynamicSharedMemorySize,
                         QK_SMEM_BYTES);
    cudaFuncSetAttribute(pv_mma, cudaFuncAttributeMaxDynamicSharedMemorySize,
                         PV_SMEM_BYTES);

    pe_proj_kernel<<<dim3(PP, 2), CC>>>(Wpx, bpx, Wpy, bpy);
    proj_mma<<<dim3(8, 1, 4),  256>>>(zx, Wq, bq, 64, 0);    // q
    proj_mma<<<dim3(8, 1, 32), 256>>>(zy, Wk, bk, 64, 1);    // k
    proj_mma<<<dim3(8, 4, 32), 256>>>(zy, Wv, bv, 256, 2);   // v (transposed out)
    qk_softmax<<<dim3(PP / 64, NK / 64), 256, QK_SMEM_BYTES>>>();
    pv_mma<<<dim3(8, 2, 16), 256, PV_SMEM_BYTES>>>();
    reduce4<<<(BB * PP * CC / 4) / 256, 256>>>(out);
}

// round 9
// speedup vs baseline: 1.6897x; 1.0246x over previous
#include <cuda_runtime.h>
#include <cuda_bf16.h>
#include <cstdint>

// Fixed shapes
#define BB 4
#define CC 256
#define PP 1024
#define NK 8192
#define AA 64
#define PL (PP * NK)
#define PVSPLIT 4

// -------- device scratch --------
__device__ unsigned g_q[BB * PP * AA / 2];            // 0.5 MB  [b][p][a/2] bf16x2
__device__ unsigned g_k[BB * NK * AA / 2];            //  4 MB   [b][k][a/2]
__device__ unsigned g_vt[BB * CC * NK / 2];           // 16 MB   [b][c][k/2]  (V^T)
__device__ unsigned g_P[(size_t)BB * PL / 2];         // 64 MB   [b][p][k/2]
__device__ float g_peq[PP * AA];
__device__ float g_pek[PP * AA];
__device__ float g_part[PVSPLIT * BB * PP * CC];      // 16 MB fp32 partials

// -------- helpers --------
__device__ __forceinline__ uint32_t f2tf(float f) {
    uint32_t r;
    asm("cvt.rna.tf32.f32 %0, %1;" : "=r"(r) : "f"(f));
    return r;
}
__device__ __forceinline__ unsigned pack_bf16(float lo, float hi) {
    unsigned r;
    asm("cvt.rn.bf16x2.f32 %0, %1, %2;" : "=r"(r) : "f"(hi), "f"(lo));
    return r;
}
__device__ __forceinline__ void mma8(float* c, const uint32_t* a, const uint32_t* b) {
    asm volatile("mma.sync.aligned.m16n8k8.row.col.f32.tf32.tf32.f32 "
                 "{%0,%1,%2,%3}, {%4,%5,%6,%7}, {%8,%9}, {%0,%1,%2,%3};"
                 : "+f"(c[0]), "+f"(c[1]), "+f"(c[2]), "+f"(c[3])
                 : "r"(a[0]), "r"(a[1]), "r"(a[2]), "r"(a[3]), "r"(b[0]), "r"(b[1]));
}
__device__ __forceinline__ void mma16(float* c, const unsigned* a, const unsigned* b) {
    asm volatile("mma.sync.aligned.m16n8k16.row.col.f32.bf16.bf16.f32 "
                 "{%0,%1,%2,%3}, {%4,%5,%6,%7}, {%8,%9}, {%0,%1,%2,%3};"
                 : "+f"(c[0]), "+f"(c[1]), "+f"(c[2]), "+f"(c[3])
                 : "r"(a[0]), "r"(a[1]), "r"(a[2]), "r"(a[3]), "r"(b[0]), "r"(b[1]));
}
__device__ __forceinline__ void ldm_x4(unsigned* r, uint32_t addr) {
    asm volatile("ldmatrix.sync.aligned.m8n8.x4.shared.b16 {%0,%1,%2,%3}, [%4];"
                 : "=r"(r[0]), "=r"(r[1]), "=r"(r[2]), "=r"(r[3]) : "r"(addr));
}
__device__ __forceinline__ uint4 cvt4(float4 v) {
    uint4 r;
    r.x = f2tf(v.x); r.y = f2tf(v.y); r.z = f2tf(v.z); r.w = f2tf(v.w);
    return r;
}
__device__ __forceinline__ void cp_async16(uint32_t dst, const void* src) {
    asm volatile("cp.async.cg.shared.global [%0], [%1], 16;" :: "r"(dst), "l"(src));
}
#define CP_COMMIT() asm volatile("cp.async.commit_group;")
template<int N> __device__ __forceinline__ void cp_wait() {
    asm volatile("cp.async.wait_group %0;" :: "n"(N));
}
__device__ __forceinline__ uint32_t smem_u32(const void* p) {
    return (uint32_t)__cvta_generic_to_shared(p);
}

// Lane-offset builders for ldmatrix address patterns (row stride 36 uints).
__device__ __forceinline__ int laneA_off(int L) {
    return ((((L >> 3) & 1) * 8 + (L & 7)) * 36 + (L >> 4) * 4) * 4;
}
__device__ __forceinline__ int laneB_off(int L) {
    return (((L >> 4) * 8 + (L & 7)) * 36 + ((L >> 3) & 1) * 4) * 4;
}

// ============================================================================
// Kernel 1: positional-encoding projections pe_q / pe_k  [1024, 64] (fp32)
// ============================================================================
__global__ void pe_proj_kernel(const float* __restrict__ Wpx, const float* __restrict__ bpx,
                               const float* __restrict__ Wpy, const float* __restrict__ bpy) {
    int p = blockIdx.x;
    int y = p >> 5, x = p & 31;
    const float* W = blockIdx.y ? Wpy : Wpx;
    const float* bb = blockIdx.y ? bpy : bpx;
    float* outp = blockIdx.y ? g_pek : g_peq;

    __shared__ float pe[CC];
    int c = threadIdx.x;
    {
        int pos = (c < 128) ? y : x;
        int idx = (c < 128) ? c : (c - 128);
        int j = idx >> 1;
        float ang = (float)pos * expf(-logf(10000.0f) * (float)j / 64.0f);
        pe[c] = (idx & 1) ? cosf(ang) : sinf(ang);
    }
    __syncthreads();
    if (c < AA) {
        float s = 0.0f;
        #pragma unroll 8
        for (int i = 0; i < CC; i++) s += pe[i] * W[c * CC + i];
        outp[p * AA + c] = s + bb[c];
    }
}

// ============================================================================
// Kernel 2: tf32 projection GEMM -> bf16 outputs, register-pipelined loads.
// ============================================================================
__global__ __launch_bounds__(256) void proj_mma(const float* __restrict__ A,
                                                const float* __restrict__ W,
                                                const float* __restrict__ bias,
                                                int N, int mode) {
    __shared__ uint32_t As[32][136];
    __shared__ uint32_t Ws[64][36];

    int z = blockIdx.z;
    A += (size_t)z * CC * PP;
    int m0 = blockIdx.x * 128, n0 = blockIdx.y * 64;

    int tid = threadIdx.x;
    int wid = tid >> 5;
    int g = (tid >> 2) & 7, tg = tid & 3;
    int mbase = (wid >> 1) * 32;
    int nbase = (wid & 1) * 32;

    float acc[2][4][4];
    #pragma unroll
    for (int i = 0; i < 2; i++)
        #pragma unroll
        for (int j = 0; j < 4; j++)
            #pragma unroll
            for (int r = 0; r < 4; r++) acc[i][j][r] = 0.0f;

    float4 ar[4], wr[2];
    auto ldA = [&](int c0) {
        #pragma unroll
        for (int i = 0; i < 4; i++) {
            int idx = i * 256 + tid;
            int row = idx >> 5, c4 = idx & 31;
            ar[i] = *(const float4*)&A[(size_t)(c0 + row) * PP + m0 + c4 * 4];
        }
    };
    auto ldW = [&](int c0) {
        #pragma unroll
        for (int i = 0; i < 2; i++) {
            int idx = i * 256 + tid;
            int row = idx >> 3, c4 = idx & 7;
            wr[i] = *(const float4*)&W[(size_t)(n0 + row) * CC + c0 + c4 * 4];
        }
    };

    ldA(0); ldW(0);

    for (int c0 = 0; c0 < CC; c0 += 32) {
        #pragma unroll
        for (int i = 0; i < 4; i++) {
            int idx = i * 256 + tid;
            int row = idx >> 5, c4 = idx & 31;
            *(uint4*)&As[row][c4 * 4] = cvt4(ar[i]);
        }
        #pragma unroll
        for (int i = 0; i < 2; i++) {
            int idx = i * 256 + tid;
            int row = idx >> 3, c4 = idx & 7;
            *(uint4*)&Ws[row][c4 * 4] = cvt4(wr[i]);
        }
        __syncthreads();

        if (c0 + 32 < CC) { ldA(c0 + 32); ldW(c0 + 32); }

        #pragma unroll
        for (int ks = 0; ks < 4; ks++) {
            int k0 = ks * 8;
            uint32_t af[2][4], bf[4][2];
            #pragma unroll
            for (int mt = 0; mt < 2; mt++) {
                int mr = mbase + mt * 16;
                af[mt][0] = As[k0 + tg][mr + g];
                af[mt][1] = As[k0 + tg][mr + g + 8];
                af[mt][2] = As[k0 + tg + 4][mr + g];
                af[mt][3] = As[k0 + tg + 4][mr + g + 8];
            }
            #pragma unroll
            for (int nt = 0; nt < 4; nt++) {
                int nr = nbase + nt * 8;
                bf[nt][0] = Ws[nr + g][k0 + tg];
                bf[nt][1] = Ws[nr + g][k0 + tg + 4];
            }
            #pragma unroll
            for (int mt = 0; mt < 2; mt++)
                #pragma unroll
                for (int nt = 0; nt < 4; nt++)
                    mma8(acc[mt][nt], af[mt], bf[nt]);
        }
        __syncthreads();
    }

    if (mode < 2) {
        const float* extra = (mode == 0) ? g_peq : g_pek;
        unsigned* C = (mode == 0 ? g_q : g_k) + (size_t)z * PP * (N / 2);
        #pragma unroll
        for (int mt = 0; mt < 2; mt++) {
            int r0 = m0 + mbase + mt * 16 + g;
            #pragma unroll
            for (int nt = 0; nt < 4; nt++) {
                int col = n0 + nbase + nt * 8 + 2 * tg;
                float b0 = bias[col], b1 = bias[col + 1];
                float e00 = extra[r0 * AA + col],       e01 = extra[r0 * AA + col + 1];
                float e10 = extra[(r0 + 8) * AA + col], e11 = extra[(r0 + 8) * AA + col + 1];
                C[r0 * (N / 2) + col / 2] =
                    pack_bf16(acc[mt][nt][0] + b0 + e00, acc[mt][nt][1] + b1 + e01);
                C[(r0 + 8) * (N / 2) + col / 2] =
                    pack_bf16(acc[mt][nt][2] + b0 + e10, acc[mt][nt][3] + b1 + e11);
            }
        }
    } else {
        __nv_bfloat16* Cs = (__nv_bfloat16*)&As[0][0];   // 64 x 132 bf16 rows
        #pragma unroll
        for (int mt = 0; mt < 2; mt++) {
            int r0 = mbase + mt * 16 + g;
            #pragma unroll
            for (int nt = 0; nt < 4; nt++) {
                int col = nbase + nt * 8 + 2 * tg;
                float b0 = bias[n0 + col], b1 = bias[n0 + col + 1];
                Cs[(col)     * 132 + r0]     = __float2bfloat16(acc[mt][nt][0] + b0);
                Cs[(col + 1) * 132 + r0]     = __float2bfloat16(acc[mt][nt][1] + b1);
                Cs[(col)     * 132 + r0 + 8] = __float2bfloat16(acc[mt][nt][2] + b0);
                Cs[(col + 1) * 132 + r0 + 8] = __float2bfloat16(acc[mt][nt][3] + b1);
            }
        }
        __syncthreads();
        int b = z >> 3, page = z & 7;
        const unsigned* Csu = (const unsigned*)Cs;
        #pragma unroll
        for (int j = 0; j < 16; j++) {
            int f = j * 256 + tid;
            int n = f >> 6, u = f & 63;
            g_vt[(size_t)(b * CC + n0 + n) * (NK / 2) + page * 512 + m0 / 2 + u] =
                Csu[n * 66 + u];
        }
    }
}

// ============================================================================
// Kernel 3: QK^T (bf16, ldmatrix) + register-local batch softmax -> P (bf16).
// 2 CTAs/SM; cp.async tile fill. Grid (16, 128), 256 threads.
// ============================================================================
#define QK_TILE (4 * 64 * 36)
#define QK_SMEM_BYTES (2 * QK_TILE * 4)

__global__ __launch_bounds__(256, 2) void qk_softmax() {
    extern __shared__ uint32_t sm[];
    const uint32_t sb = smem_u32(sm);

    const int tid = threadIdx.x;
    const int wid = tid >> 5;
    const int L = tid & 31;
    const int g = (tid >> 2) & 7, tg = tid & 3;
    const int qbase = blockIdx.x * 64, kbase = blockIdx.y * 64;

    // async fill of Q and K tiles (4 batches x 64 rows x 8 uint4 each)
    #pragma unroll
    for (int j = 0; j < 8; j++) {
        int f = j * 256 + tid;
        int row = f >> 3, a4 = f & 7;
        int b = row >> 6, r = row & 63;
        cp_async16(sb + (row * 36 + a4 * 4) * 4,
                   &g_q[((b << 10) + qbase + r) * 32 + a4 * 4]);
        cp_async16(sb + (QK_TILE + row * 36 + a4 * 4) * 4,
                   &g_k[((b << 13) + kbase + r) * 32 + a4 * 4]);
    }
    CP_COMMIT();
    cp_wait<0>();
    __syncthreads();

    const int wm = wid >> 2, wn = wid & 3;
    const int qrow0 = wm * 32, kcol0 = wn * 16;

    const int aoff = laneA_off(L);
    const int boff = laneB_off(L);
    const uint32_t qa_base = sb + qrow0 * 36 * 4 + aoff;
    const uint32_t kb_base = sb + QK_TILE * 4 + kcol0 * 36 * 4 + boff;

    float acc[4][2][2][4];
    #pragma unroll
    for (int b = 0; b < 4; b++)
        #pragma unroll
        for (int i = 0; i < 2; i++)
            #pragma unroll
            for (int j = 0; j < 2; j++)
                #pragma unroll
                for (int r = 0; r < 4; r++) acc[b][i][j][r] = 0.0f;

    #pragma unroll
    for (int ks = 0; ks < 4; ks++) {
        int k0b = ks * 32;
        #pragma unroll
        for (int b = 0; b < 4; b++) {
            unsigned af[2][4], bf[4];
            ldm_x4(af[0], qa_base + b * 9216 + k0b);
            ldm_x4(af[1], qa_base + b * 9216 + 16 * 36 * 4 + k0b);
            ldm_x4(bf,    kb_base + b * 9216 + k0b);
            #pragma unroll
            for (int mt = 0; mt < 2; mt++)
                #pragma unroll
                for (int nt = 0; nt < 2; nt++)
                    mma16(acc[b][mt][nt], af[mt], bf + nt * 2);
        }
    }

    __syncthreads();
    uint32_t* Ps = sm;

    #pragma unroll
    for (int mt = 0; mt < 2; mt++) {
        int lo = qrow0 + mt * 16 + g;
        #pragma unroll
        for (int nt = 0; nt < 2; nt++) {
            int cu = kcol0 / 2 + nt * 4 + tg;
            float p[4][4];
            #pragma unroll
            for (int r = 0; r < 4; r++) {
                float s0 = acc[0][mt][nt][r] * 0.125f;
                float s1 = acc[1][mt][nt][r] * 0.125f;
                float s2 = acc[2][mt][nt][r] * 0.125f;
                float s3 = acc[3][mt][nt][r] * 0.125f;
                float m = fmaxf(fmaxf(s0, s1), fmaxf(s2, s3));
                float e0 = __expf(s0 - m), e1 = __expf(s1 - m);
                float e2 = __expf(s2 - m), e3 = __expf(s3 - m);
                float rv = 1.0f / (e0 + e1 + e2 + e3);
                p[r][0] = e0 * rv; p[r][1] = e1 * rv;
                p[r][2] = e2 * rv; p[r][3] = e3 * rv;
            }
            #pragma unroll
            for (int b = 0; b < 4; b++) {
                Ps[b * 2304 + lo * 36 + cu]       = pack_bf16(p[0][b], p[1][b]);
                Ps[b * 2304 + (lo + 8) * 36 + cu] = pack_bf16(p[2][b], p[3][b]);
            }
        }
    }
    __syncthreads();

    #pragma unroll
    for (int j = 0; j < 8; j++) {
        int f = j * 256 + tid;
        int b = f >> 9, r = (f >> 3) & 63, q4 = f & 7;
        uint4 val = *(const uint4*)&Ps[b * 2304 + r * 36 + q4 * 4];
        *(uint4*)&g_P[(size_t)b * (PL / 2) + (size_t)(qbase + r) * (NK / 2) + kbase / 2 + q4 * 4] = val;
    }
}

// ============================================================================
// Kernel 4: O = P @ V (bf16, ldmatrix), split-K=4, BK=64 double-buffer.
// 2 CTAs/SM. BM=128, BN=128(c). 8 warps (4m x 2n). grid (8, 2, 16).
// ============================================================================
#define PS_BUF (128 * 36)
#define VS_BUF (128 * 36)
#define STAGE  (PS_BUF + VS_BUF)
#define PV_SMEM_BYTES (2 * STAGE * 4)   // 73728 B

__global__ __launch_bounds__(256, 2) void pv_mma() {
    extern __shared__ uint32_t sm[];
    const uint32_t sb = smem_u32(sm);

    int b = blockIdx.z >> 2;
    int split = blockIdx.z & 3;
    int m0 = blockIdx.x * 128, n0 = blockIdx.y * 128;
    int tid = threadIdx.x;
    int wid = tid >> 5;
    const int L = tid & 31;
    int g = (tid >> 2) & 7, tg = tid & 3;
    int mbase = (wid >> 1) * 32;
    int nbase = (wid & 1) * 64;

    const unsigned* Pu = g_P  + (size_t)b * (PL / 2);
    const unsigned* Vu = g_vt + (size_t)b * CC * (NK / 2);

    const int kstart = split * (NK / PVSPLIT);
    const int NIT = (NK / PVSPLIT) / 64;   // 32

    auto prefetch = [&](int it, int buf) {
        int kbu = (kstart + it * 64) / 2;
        #pragma unroll
        for (int j = 0; j < 4; j++) {
            int f = j * 256 + tid;
            int row = f >> 3, c4 = f & 7;
            uint32_t dst = sb + (buf * STAGE + row * 36 + c4 * 4) * 4;
            cp_async16(dst, Pu + (size_t)(m0 + row) * (NK / 2) + kbu + c4 * 4);
            uint32_t dst2 = sb + (buf * STAGE + PS_BUF + row * 36 + c4 * 4) * 4;
            cp_async16(dst2, Vu + (size_t)(n0 + row) * (NK / 2) + kbu + c4 * 4);
        }
        CP_COMMIT();
    };

    float acc[2][8][4];
    #pragma unroll
    for (int i = 0; i < 2; i++)
        #pragma unroll
        for (int j = 0; j < 8; j++)
            #pragma unroll
            for (int r = 0; r < 4; r++) acc[i][j][r] = 0.0f;

    const int aoff = laneA_off(L);
    const int boff = laneB_off(L);
    const uint32_t pa_base = sb + mbase * 36 * 4 + aoff;
    const uint32_t vb_base = sb + PS_BUF * 4 + nbase * 36 * 4 + boff;

    prefetch(0, 0);
    prefetch(1, 1);

    for (int it = 0; it < NIT; it++) {
        int buf = it & 1;
        if (it + 1 < NIT) cp_wait<1>(); else cp_wait<0>();
        __syncthreads();

        uint32_t stg = (uint32_t)(buf * STAGE * 4);
        #pragma unroll
        for (int ks = 0; ks < 4; ks++) {
            int k0b = ks * 32;
            unsigned af[2][4], bf[4][4];
            ldm_x4(af[0], pa_base + stg + k0b);
            ldm_x4(af[1], pa_base + stg + 16 * 36 * 4 + k0b);
            #pragma unroll
            for (int j = 0; j < 4; j++)
                ldm_x4(bf[j], vb_base + stg + j * 16 * 36 * 4 + k0b);
            #pragma unroll
            for (int mt = 0; mt < 2; mt++)
                #pragma unroll
                for (int nt = 0; nt < 8; nt++)
                    mma16(acc[mt][nt], af[mt], bf[nt >> 1] + (nt & 1) * 2);
        }
        __syncthreads();
        if (it + 2 < NIT) prefetch(it + 2, buf);
    }

    float* part = g_part + (size_t)split * (BB * PP * CC);
    #pragma unroll
    for (int mt = 0; mt < 2; mt++) {
        int r0 = m0 + mbase + mt * 16 + g;
        #pragma unroll
        for (int nt = 0; nt < 8; nt++) {
            int col = n0 + nbase + nt * 8 + 2 * tg;
            *(float2*)&part[(size_t)((b << 10) + r0) * CC + col] =
                make_float2(acc[mt][nt][0], acc[mt][nt][1]);
            *(float2*)&part[(size_t)((b << 10) + r0 + 8) * CC + col] =
                make_float2(acc[mt][nt][2], acc[mt][nt][3]);
        }
    }
}

// ============================================================================
// Kernel 5: deterministic 4-way split-K reduction into d_out ([b][p][c])
// ============================================================================
__global__ void reduce4(float* __restrict__ out) {
    int i = blockIdx.x * blockDim.x + threadIdx.x;
    const float4* p = (const float4*)g_part;
    const int plane = BB * PP * CC / 4;
    float4 s = p[i];
    #pragma unroll
    for (int sp = 1; sp < PVSPLIT; sp++) {
        float4 t = p[(size_t)sp * plane + i];
        s.x += t.x; s.y += t.y; s.z += t.z; s.w += t.w;
    }
    ((float4*)out)[i] = s;
}

// ============================================================================
extern "C" void kernel_launch(void* const* d_in, const int* in_sizes, int n_in,
                              void* d_out, int out_size) {
    const float* zx  = (const float*)d_in[0];
    const float* zy  = (const float*)d_in[1];
    const float* Wq  = (const float*)d_in[2];
    const float* bq  = (const float*)d_in[3];
    const float* Wpx = (const float*)d_in[4];
    const float* bpx = (const float*)d_in[5];
    const float* Wk  = (const float*)d_in[6];
    const float* bk  = (const float*)d_in[7];
    const float* Wpy = (const float*)d_in[8];
    const float* bpy = (const float*)d_in[9];
    const float* Wv  = (const float*)d_in[10];
    const float* bv  = (const float*)d_in[11];
    float* out = (float*)d_out;

    cudaFuncSetAttribute(qk_softmax, cudaFuncAttributeMaxDynamicSharedMemorySize,
                         QK_SMEM_BYTES);
    cudaFuncSetAttribute(pv_mma, cudaFuncAttributeMaxDynamicSharedMemorySize,
                         PV_SMEM_BYTES);

    pe_proj_kernel<<<dim3(PP, 2), CC>>>(Wpx, bpx, Wpy, bpy);
    proj_mma<<<dim3(8, 1, 4),  256>>>(zx, Wq, bq, 64, 0);    // q
    proj_mma<<<dim3(8, 1, 32), 256>>>(zy, Wk, bk, 64, 1);    // k
    proj_mma<<<dim3(8, 4, 32), 256>>>(zy, Wv, bv, 256, 2);   // v (transposed out)
    qk_softmax<<<dim3(PP / 64, NK / 64), 256, QK_SMEM_BYTES>>>();
    pv_mma<<<dim3(8, 2, 16), 256, PV_SMEM_BYTES>>>();
    reduce4<<<(BB * PP * CC / 4) / 256, 256>>>(out);
}

// round 10
// speedup vs baseline: 1.7074x; 1.0104x over previous
#include <cuda_runtime.h>
#include <cuda_bf16.h>
#include <cstdint>

// Fixed shapes
#define BB 4
#define CC 256
#define PP 1024
#define NK 8192
#define AA 64
#define PL (PP * NK)
#define PVSPLIT 4

// -------- device scratch --------
__device__ unsigned g_q[BB * PP * AA / 2];            // 0.5 MB  [b][p][a/2] bf16x2
__device__ unsigned g_k[BB * NK * AA / 2];            //  4 MB   [b][k][a/2]
__device__ unsigned g_vt[BB * CC * NK / 2];           // 16 MB   [b][c][k/2]  (V^T)
__device__ unsigned g_P[(size_t)BB * PL / 2];         // 64 MB   [b][p][k/2]
__device__ float g_peq[PP * AA];
__device__ float g_pek[PP * AA];
__device__ float g_part[PVSPLIT * BB * PP * CC];      // 16 MB fp32 partials

// -------- helpers --------
__device__ __forceinline__ uint32_t f2tf(float f) {
    uint32_t r;
    asm("cvt.rna.tf32.f32 %0, %1;" : "=r"(r) : "f"(f));
    return r;
}
__device__ __forceinline__ unsigned pack_bf16(float lo, float hi) {
    unsigned r;
    asm("cvt.rn.bf16x2.f32 %0, %1, %2;" : "=r"(r) : "f"(hi), "f"(lo));
    return r;
}
__device__ __forceinline__ void mma8(float* c, const uint32_t* a, const uint32_t* b) {
    asm volatile("mma.sync.aligned.m16n8k8.row.col.f32.tf32.tf32.f32 "
                 "{%0,%1,%2,%3}, {%4,%5,%6,%7}, {%8,%9}, {%0,%1,%2,%3};"
                 : "+f"(c[0]), "+f"(c[1]), "+f"(c[2]), "+f"(c[3])
                 : "r"(a[0]), "r"(a[1]), "r"(a[2]), "r"(a[3]), "r"(b[0]), "r"(b[1]));
}
__device__ __forceinline__ void mma16(float* c, const unsigned* a, const unsigned* b) {
    asm volatile("mma.sync.aligned.m16n8k16.row.col.f32.bf16.bf16.f32 "
                 "{%0,%1,%2,%3}, {%4,%5,%6,%7}, {%8,%9}, {%0,%1,%2,%3};"
                 : "+f"(c[0]), "+f"(c[1]), "+f"(c[2]), "+f"(c[3])
                 : "r"(a[0]), "r"(a[1]), "r"(a[2]), "r"(a[3]), "r"(b[0]), "r"(b[1]));
}
__device__ __forceinline__ void ldm_x4(unsigned* r, uint32_t addr) {
    asm volatile("ldmatrix.sync.aligned.m8n8.x4.shared.b16 {%0,%1,%2,%3}, [%4];"
                 : "=r"(r[0]), "=r"(r[1]), "=r"(r[2]), "=r"(r[3]) : "r"(addr));
}
__device__ __forceinline__ uint4 cvt4(float4 v) {
    uint4 r;
    r.x = f2tf(v.x); r.y = f2tf(v.y); r.z = f2tf(v.z); r.w = f2tf(v.w);
    return r;
}
__device__ __forceinline__ void cp_async16(uint32_t dst, const void* src) {
    asm volatile("cp.async.cg.shared.global [%0], [%1], 16;" :: "r"(dst), "l"(src));
}
#define CP_COMMIT() asm volatile("cp.async.commit_group;")
template<int N> __device__ __forceinline__ void cp_wait() {
    asm volatile("cp.async.wait_group %0;" :: "n"(N));
}
__device__ __forceinline__ uint32_t smem_u32(const void* p) {
    return (uint32_t)__cvta_generic_to_shared(p);
}

// Lane-offset builders for ldmatrix address patterns (row stride 36 uints).
__device__ __forceinline__ int laneA_off(int L) {
    return ((((L >> 3) & 1) * 8 + (L & 7)) * 36 + (L >> 4) * 4) * 4;
}
__device__ __forceinline__ int laneB_off(int L) {
    return (((L >> 4) * 8 + (L & 7)) * 36 + ((L >> 3) & 1) * 4) * 4;
}

// ============================================================================
// Kernel 1: positional-encoding projections pe_q / pe_k  [1024, 64] (fp32)
// ============================================================================
__global__ void pe_proj_kernel(const float* __restrict__ Wpx, const float* __restrict__ bpx,
                               const float* __restrict__ Wpy, const float* __restrict__ bpy) {
    int p = blockIdx.x;
    int y = p >> 5, x = p & 31;
    const float* W = blockIdx.y ? Wpy : Wpx;
    const float* bb = blockIdx.y ? bpy : bpx;
    float* outp = blockIdx.y ? g_pek : g_peq;

    __shared__ float pe[CC];
    int c = threadIdx.x;
    {
        int pos = (c < 128) ? y : x;
        int idx = (c < 128) ? c : (c - 128);
        int j = idx >> 1;
        float ang = (float)pos * expf(-logf(10000.0f) * (float)j / 64.0f);
        pe[c] = (idx & 1) ? cosf(ang) : sinf(ang);
    }
    __syncthreads();
    if (c < AA) {
        float s = 0.0f;
        #pragma unroll 8
        for (int i = 0; i < CC; i++) s += pe[i] * W[c * CC + i];
        outp[p * AA + c] = s + bb[c];
    }
}

// ============================================================================
// Kernel 2: tf32 projection GEMM -> bf16 outputs, register-pipelined loads.
// ============================================================================
__global__ __launch_bounds__(256) void proj_mma(const float* __restrict__ A,
                                                const float* __restrict__ W,
                                                const float* __restrict__ bias,
                                                int N, int mode) {
    __shared__ uint32_t As[32][136];
    __shared__ uint32_t Ws[64][36];

    int z = blockIdx.z;
    A += (size_t)z * CC * PP;
    int m0 = blockIdx.x * 128, n0 = blockIdx.y * 64;

    int tid = threadIdx.x;
    int wid = tid >> 5;
    int g = (tid >> 2) & 7, tg = tid & 3;
    int mbase = (wid >> 1) * 32;
    int nbase = (wid & 1) * 32;

    float acc[2][4][4];
    #pragma unroll
    for (int i = 0; i < 2; i++)
        #pragma unroll
        for (int j = 0; j < 4; j++)
            #pragma unroll
            for (int r = 0; r < 4; r++) acc[i][j][r] = 0.0f;

    float4 ar[4], wr[2];
    auto ldA = [&](int c0) {
        #pragma unroll
        for (int i = 0; i < 4; i++) {
            int idx = i * 256 + tid;
            int row = idx >> 5, c4 = idx & 31;
            ar[i] = *(const float4*)&A[(size_t)(c0 + row) * PP + m0 + c4 * 4];
        }
    };
    auto ldW = [&](int c0) {
        #pragma unroll
        for (int i = 0; i < 2; i++) {
            int idx = i * 256 + tid;
            int row = idx >> 3, c4 = idx & 7;
            wr[i] = *(const float4*)&W[(size_t)(n0 + row) * CC + c0 + c4 * 4];
        }
    };

    ldA(0); ldW(0);

    for (int c0 = 0; c0 < CC; c0 += 32) {
        #pragma unroll
        for (int i = 0; i < 4; i++) {
            int idx = i * 256 + tid;
            int row = idx >> 5, c4 = idx & 31;
            *(uint4*)&As[row][c4 * 4] = cvt4(ar[i]);
        }
        #pragma unroll
        for (int i = 0; i < 2; i++) {
            int idx = i * 256 + tid;
            int row = idx >> 3, c4 = idx & 7;
            *(uint4*)&Ws[row][c4 * 4] = cvt4(wr[i]);
        }
        __syncthreads();

        if (c0 + 32 < CC) { ldA(c0 + 32); ldW(c0 + 32); }

        #pragma unroll
        for (int ks = 0; ks < 4; ks++) {
            int k0 = ks * 8;
            uint32_t af[2][4], bf[4][2];
            #pragma unroll
            for (int mt = 0; mt < 2; mt++) {
                int mr = mbase + mt * 16;
                af[mt][0] = As[k0 + tg][mr + g];
                af[mt][1] = As[k0 + tg][mr + g + 8];
                af[mt][2] = As[k0 + tg + 4][mr + g];
                af[mt][3] = As[k0 + tg + 4][mr + g + 8];
            }
            #pragma unroll
            for (int nt = 0; nt < 4; nt++) {
                int nr = nbase + nt * 8;
                bf[nt][0] = Ws[nr + g][k0 + tg];
                bf[nt][1] = Ws[nr + g][k0 + tg + 4];
            }
            #pragma unroll
            for (int mt = 0; mt < 2; mt++)
                #pragma unroll
                for (int nt = 0; nt < 4; nt++)
                    mma8(acc[mt][nt], af[mt], bf[nt]);
        }
        __syncthreads();
    }

    if (mode < 2) {
        const float* extra = (mode == 0) ? g_peq : g_pek;
        unsigned* C = (mode == 0 ? g_q : g_k) + (size_t)z * PP * (N / 2);
        #pragma unroll
        for (int mt = 0; mt < 2; mt++) {
            int r0 = m0 + mbase + mt * 16 + g;
            #pragma unroll
            for (int nt = 0; nt < 4; nt++) {
                int col = n0 + nbase + nt * 8 + 2 * tg;
                float b0 = bias[col], b1 = bias[col + 1];
                float e00 = extra[r0 * AA + col],       e01 = extra[r0 * AA + col + 1];
                float e10 = extra[(r0 + 8) * AA + col], e11 = extra[(r0 + 8) * AA + col + 1];
                C[r0 * (N / 2) + col / 2] =
                    pack_bf16(acc[mt][nt][0] + b0 + e00, acc[mt][nt][1] + b1 + e01);
                C[(r0 + 8) * (N / 2) + col / 2] =
                    pack_bf16(acc[mt][nt][2] + b0 + e10, acc[mt][nt][3] + b1 + e11);
            }
        }
    } else {
        __nv_bfloat16* Cs = (__nv_bfloat16*)&As[0][0];   // 64 x 132 bf16 rows
        #pragma unroll
        for (int mt = 0; mt < 2; mt++) {
            int r0 = mbase + mt * 16 + g;
            #pragma unroll
            for (int nt = 0; nt < 4; nt++) {
                int col = nbase + nt * 8 + 2 * tg;
                float b0 = bias[n0 + col], b1 = bias[n0 + col + 1];
                Cs[(col)     * 132 + r0]     = __float2bfloat16(acc[mt][nt][0] + b0);
                Cs[(col + 1) * 132 + r0]     = __float2bfloat16(acc[mt][nt][1] + b1);
                Cs[(col)     * 132 + r0 + 8] = __float2bfloat16(acc[mt][nt][2] + b0);
                Cs[(col + 1) * 132 + r0 + 8] = __float2bfloat16(acc[mt][nt][3] + b1);
            }
        }
        __syncthreads();
        int b = z >> 3, page = z & 7;
        const unsigned* Csu = (const unsigned*)Cs;
        #pragma unroll
        for (int j = 0; j < 16; j++) {
            int f = j * 256 + tid;
            int n = f >> 6, u = f & 63;
            g_vt[(size_t)(b * CC + n0 + n) * (NK / 2) + page * 512 + m0 / 2 + u] =
                Csu[n * 66 + u];
        }
    }
}

// ============================================================================
// Kernel 3: QK^T (bf16, ldmatrix) + register-local batch softmax -> P (bf16).
// 2 CTAs/SM; cp.async tile fill. Grid (16, 128), 256 threads. (unchanged)
// ============================================================================
#define QK_TILE (4 * 64 * 36)
#define QK_SMEM_BYTES (2 * QK_TILE * 4)

__global__ __launch_bounds__(256, 2) void qk_softmax() {
    extern __shared__ uint32_t sm[];
    const uint32_t sb = smem_u32(sm);

    const int tid = threadIdx.x;
    const int wid = tid >> 5;
    const int L = tid & 31;
    const int g = (tid >> 2) & 7, tg = tid & 3;
    const int qbase = blockIdx.x * 64, kbase = blockIdx.y * 64;

    #pragma unroll
    for (int j = 0; j < 8; j++) {
        int f = j * 256 + tid;
        int row = f >> 3, a4 = f & 7;
        int b = row >> 6, r = row & 63;
        cp_async16(sb + (row * 36 + a4 * 4) * 4,
                   &g_q[((b << 10) + qbase + r) * 32 + a4 * 4]);
        cp_async16(sb + (QK_TILE + row * 36 + a4 * 4) * 4,
                   &g_k[((b << 13) + kbase + r) * 32 + a4 * 4]);
    }
    CP_COMMIT();
    cp_wait<0>();
    __syncthreads();

    const int wm = wid >> 2, wn = wid & 3;
    const int qrow0 = wm * 32, kcol0 = wn * 16;

    const int aoff = laneA_off(L);
    const int boff = laneB_off(L);
    const uint32_t qa_base = sb + qrow0 * 36 * 4 + aoff;
    const uint32_t kb_base = sb + QK_TILE * 4 + kcol0 * 36 * 4 + boff;

    float acc[4][2][2][4];
    #pragma unroll
    for (int b = 0; b < 4; b++)
        #pragma unroll
        for (int i = 0; i < 2; i++)
            #pragma unroll
            for (int j = 0; j < 2; j++)
                #pragma unroll
                for (int r = 0; r < 4; r++) acc[b][i][j][r] = 0.0f;

    #pragma unroll
    for (int ks = 0; ks < 4; ks++) {
        int k0b = ks * 32;
        #pragma unroll
        for (int b = 0; b < 4; b++) {
            unsigned af[2][4], bf[4];
            ldm_x4(af[0], qa_base + b * 9216 + k0b);
            ldm_x4(af[1], qa_base + b * 9216 + 16 * 36 * 4 + k0b);
            ldm_x4(bf,    kb_base + b * 9216 + k0b);
            #pragma unroll
            for (int mt = 0; mt < 2; mt++)
                #pragma unroll
                for (int nt = 0; nt < 2; nt++)
                    mma16(acc[b][mt][nt], af[mt], bf + nt * 2);
        }
    }

    __syncthreads();
    uint32_t* Ps = sm;

    #pragma unroll
    for (int mt = 0; mt < 2; mt++) {
        int lo = qrow0 + mt * 16 + g;
        #pragma unroll
        for (int nt = 0; nt < 2; nt++) {
            int cu = kcol0 / 2 + nt * 4 + tg;
            float p[4][4];
            #pragma unroll
            for (int r = 0; r < 4; r++) {
                float s0 = acc[0][mt][nt][r] * 0.125f;
                float s1 = acc[1][mt][nt][r] * 0.125f;
                float s2 = acc[2][mt][nt][r] * 0.125f;
                float s3 = acc[3][mt][nt][r] * 0.125f;
                float m = fmaxf(fmaxf(s0, s1), fmaxf(s2, s3));
                float e0 = __expf(s0 - m), e1 = __expf(s1 - m);
                float e2 = __expf(s2 - m), e3 = __expf(s3 - m);
                float rv = 1.0f / (e0 + e1 + e2 + e3);
                p[r][0] = e0 * rv; p[r][1] = e1 * rv;
                p[r][2] = e2 * rv; p[r][3] = e3 * rv;
            }
            #pragma unroll
            for (int b = 0; b < 4; b++) {
                Ps[b * 2304 + lo * 36 + cu]       = pack_bf16(p[0][b], p[1][b]);
                Ps[b * 2304 + (lo + 8) * 36 + cu] = pack_bf16(p[2][b], p[3][b]);
            }
        }
    }
    __syncthreads();

    #pragma unroll
    for (int j = 0; j < 8; j++) {
        int f = j * 256 + tid;
        int b = f >> 9, r = (f >> 3) & 63, q4 = f & 7;
        uint4 val = *(const uint4*)&Ps[b * 2304 + r * 36 + q4 * 4];
        *(uint4*)&g_P[(size_t)b * (PL / 2) + (size_t)(qbase + r) * (NK / 2) + kbase / 2 + q4 * 4] = val;
    }
}

// ============================================================================
// Kernel 4: O = P @ V (bf16, ldmatrix), split-K=4, BK=64, 3-STAGE pipeline
// with a single __syncthreads per iteration (prefetch issued before mma).
// 2 CTAs/SM. BM=128, BN=128(c). 8 warps (4m x 2n). grid (8, 2, 16).
// ============================================================================
#define PS_BUF (128 * 36)
#define VS_BUF (128 * 36)
#define STAGE  (PS_BUF + VS_BUF)
#define PV_SMEM_BYTES (3 * STAGE * 4)   // 110592 B

__global__ __launch_bounds__(256, 2) void pv_mma() {
    extern __shared__ uint32_t sm[];
    const uint32_t sb = smem_u32(sm);

    int b = blockIdx.z >> 2;
    int split = blockIdx.z & 3;
    int m0 = blockIdx.x * 128, n0 = blockIdx.y * 128;
    int tid = threadIdx.x;
    int wid = tid >> 5;
    const int L = tid & 31;
    int g = (tid >> 2) & 7, tg = tid & 3;
    int mbase = (wid >> 1) * 32;
    int nbase = (wid & 1) * 64;

    const unsigned* Pu = g_P  + (size_t)b * (PL / 2);
    const unsigned* Vu = g_vt + (size_t)b * CC * (NK / 2);

    const int kstart = split * (NK / PVSPLIT);
    const int NIT = (NK / PVSPLIT) / 64;   // 32

    auto prefetch = [&](int it, int stage) {
        int kbu = (kstart + it * 64) / 2;
        #pragma unroll
        for (int j = 0; j < 4; j++) {
            int f = j * 256 + tid;
            int row = f >> 3, c4 = f & 7;
            uint32_t dst = sb + (stage * STAGE + row * 36 + c4 * 4) * 4;
            cp_async16(dst, Pu + (size_t)(m0 + row) * (NK / 2) + kbu + c4 * 4);
            uint32_t dst2 = sb + (stage * STAGE + PS_BUF + row * 36 + c4 * 4) * 4;
            cp_async16(dst2, Vu + (size_t)(n0 + row) * (NK / 2) + kbu + c4 * 4);
        }
        CP_COMMIT();
    };

    float acc[2][8][4];
    #pragma unroll
    for (int i = 0; i < 2; i++)
        #pragma unroll
        for (int j = 0; j < 8; j++)
            #pragma unroll
            for (int r = 0; r < 4; r++) acc[i][j][r] = 0.0f;

    const int aoff = laneA_off(L);
    const int boff = laneB_off(L);
    const uint32_t pa_base = sb + mbase * 36 * 4 + aoff;
    const uint32_t vb_base = sb + PS_BUF * 4 + nbase * 36 * 4 + boff;

    prefetch(0, 0);
    prefetch(1, 1);

    int stage = 0;
    for (int it = 0; it < NIT; it++) {
        if (it + 1 < NIT) cp_wait<1>(); else cp_wait<0>();
        __syncthreads();
        // prefetch 2 ahead into the stage whose mma finished LAST iteration
        // (safe: the barrier above orders all warps past mma(it-1))
        if (it + 2 < NIT) {
            int ns = stage + 2; if (ns >= 3) ns -= 3;
            prefetch(it + 2, ns);
        }

        uint32_t stg = (uint32_t)(stage * STAGE * 4);
        #pragma unroll
        for (int ks = 0; ks < 4; ks++) {
            int k0b = ks * 32;
            unsigned af[2][4], bf[4][4];
            ldm_x4(af[0], pa_base + stg + k0b);
            ldm_x4(af[1], pa_base + stg + 16 * 36 * 4 + k0b);
            #pragma unroll
            for (int j = 0; j < 4; j++)
                ldm_x4(bf[j], vb_base + stg + j * 16 * 36 * 4 + k0b);
            #pragma unroll
            for (int mt = 0; mt < 2; mt++)
                #pragma unroll
                for (int nt = 0; nt < 8; nt++)
                    mma16(acc[mt][nt], af[mt], bf[nt >> 1] + (nt & 1) * 2);
        }
        if (++stage == 3) stage = 0;
    }

    float* part = g_part + (size_t)split * (BB * PP * CC);
    #pragma unroll
    for (int mt = 0; mt < 2; mt++) {
        int r0 = m0 + mbase + mt * 16 + g;
        #pragma unroll
        for (int nt = 0; nt < 8; nt++) {
            int col = n0 + nbase + nt * 8 + 2 * tg;
            __stcs((float2*)&part[(size_t)((b << 10) + r0) * CC + col],
                   make_float2(acc[mt][nt][0], acc[mt][nt][1]));
            __stcs((float2*)&part[(size_t)((b << 10) + r0 + 8) * CC + col],
                   make_float2(acc[mt][nt][2], acc[mt][nt][3]));
        }
    }
}

// ============================================================================
// Kernel 5: deterministic 4-way split-K reduction into d_out ([b][p][c])
// ============================================================================
__global__ void reduce4(float* __restrict__ out) {
    int i = blockIdx.x * blockDim.x + threadIdx.x;
    const float4* p = (const float4*)g_part;
    const int plane = BB * PP * CC / 4;
    float4 s = __ldcs(p + i);
    #pragma unroll
    for (int sp = 1; sp < PVSPLIT; sp++) {
        float4 t = __ldcs(p + (size_t)sp * plane + i);
        s.x += t.x; s.y += t.y; s.z += t.z; s.w += t.w;
    }
    ((float4*)out)[i] = s;
}

// ============================================================================
extern "C" void kernel_launch(void* const* d_in, const int* in_sizes, int n_in,
                              void* d_out, int out_size) {
    const float* zx  = (const float*)d_in[0];
    const float* zy  = (const float*)d_in[1];
    const float* Wq  = (const float*)d_in[2];
    const float* bq  = (const float*)d_in[3];
    const float* Wpx = (const float*)d_in[4];
    const float* bpx = (const float*)d_in[5];
    const float* Wk  = (const float*)d_in[6];
    const float* bk  = (const float*)d_in[7];
    const float* Wpy = (const float*)d_in[8];
    const float* bpy = (const float*)d_in[9];
    const float* Wv  = (const float*)d_in[10];
    const float* bv  = (const float*)d_in[11];
    float* out = (float*)d_out;

    cudaFuncSetAttribute(qk_softmax, cudaFuncAttributeMaxDynamicSharedMemorySize,
                         QK_SMEM_BYTES);
    cudaFuncSetAttribute(pv_mma, cudaFuncAttributeMaxDynamicSharedMemorySize,
                         PV_SMEM_BYTES);

    pe_proj_kernel<<<dim3(PP, 2), CC>>>(Wpx, bpx, Wpy, bpy);
    proj_mma<<<dim3(8, 1, 4),  256>>>(zx, Wq, bq, 64, 0);    // q
    proj_mma<<<dim3(8, 1, 32), 256>>>(zy, Wk, bk, 64, 1);    // k
    proj_mma<<<dim3(8, 4, 32), 256>>>(zy, Wv, bv, 256, 2);   // v (transposed out)
    qk_softmax<<<dim3(PP / 64, NK / 64), 256, QK_SMEM_BYTES>>>();
    pv_mma<<<dim3(8, 2, 16), 256, PV_SMEM_BYTES>>>();
    reduce4<<<(BB * PP * CC / 4) / 256, 256>>>(out);
}

// round 11
// speedup vs baseline: 1.7502x; 1.0251x over previous
#include <cuda_runtime.h>
#include <cuda_bf16.h>
#include <cstdint>

// Fixed shapes
#define BB 4
#define CC 256
#define PP 1024
#define NK 8192
#define AA 64
#define PL (PP * NK)
#define PVSPLIT 4

// -------- device scratch --------
__device__ unsigned g_q[BB * PP * AA / 2];            // 0.5 MB  [b][p][a/2] bf16x2
__device__ unsigned g_k[BB * NK * AA / 2];            //  4 MB   [b][k][a/2]
__device__ unsigned g_vt[BB * CC * NK / 2];           // 16 MB   [b][c][k/2]  (V^T)
__device__ unsigned g_P[(size_t)BB * PL / 2];         // 64 MB   [b][p][k/2]
__device__ float g_peq[PP * AA];
__device__ float g_pek[PP * AA];
__device__ float g_part[PVSPLIT * BB * PP * CC];      // 16 MB fp32 partials

// -------- helpers --------
__device__ __forceinline__ uint32_t f2tf(float f) {
    uint32_t r;
    asm("cvt.rna.tf32.f32 %0, %1;" : "=r"(r) : "f"(f));
    return r;
}
__device__ __forceinline__ unsigned pack_bf16(float lo, float hi) {
    unsigned r;
    asm("cvt.rn.bf16x2.f32 %0, %1, %2;" : "=r"(r) : "f"(hi), "f"(lo));
    return r;
}
__device__ __forceinline__ void mma8(float* c, const uint32_t* a, const uint32_t* b) {
    asm volatile("mma.sync.aligned.m16n8k8.row.col.f32.tf32.tf32.f32 "
                 "{%0,%1,%2,%3}, {%4,%5,%6,%7}, {%8,%9}, {%0,%1,%2,%3};"
                 : "+f"(c[0]), "+f"(c[1]), "+f"(c[2]), "+f"(c[3])
                 : "r"(a[0]), "r"(a[1]), "r"(a[2]), "r"(a[3]), "r"(b[0]), "r"(b[1]));
}
__device__ __forceinline__ void mma16(float* c, const unsigned* a, const unsigned* b) {
    asm volatile("mma.sync.aligned.m16n8k16.row.col.f32.bf16.bf16.f32 "
                 "{%0,%1,%2,%3}, {%4,%5,%6,%7}, {%8,%9}, {%0,%1,%2,%3};"
                 : "+f"(c[0]), "+f"(c[1]), "+f"(c[2]), "+f"(c[3])
                 : "r"(a[0]), "r"(a[1]), "r"(a[2]), "r"(a[3]), "r"(b[0]), "r"(b[1]));
}
__device__ __forceinline__ void ldm_x4(unsigned* r, uint32_t addr) {
    asm volatile("ldmatrix.sync.aligned.m8n8.x4.shared.b16 {%0,%1,%2,%3}, [%4];"
                 : "=r"(r[0]), "=r"(r[1]), "=r"(r[2]), "=r"(r[3]) : "r"(addr));
}
__device__ __forceinline__ uint4 cvt4(float4 v) {
    uint4 r;
    r.x = f2tf(v.x); r.y = f2tf(v.y); r.z = f2tf(v.z); r.w = f2tf(v.w);
    return r;
}
__device__ __forceinline__ void cp_async16(uint32_t dst, const void* src) {
    asm volatile("cp.async.cg.shared.global [%0], [%1], 16;" :: "r"(dst), "l"(src));
}
#define CP_COMMIT() asm volatile("cp.async.commit_group;")
template<int N> __device__ __forceinline__ void cp_wait() {
    asm volatile("cp.async.wait_group %0;" :: "n"(N));
}
__device__ __forceinline__ uint32_t smem_u32(const void* p) {
    return (uint32_t)__cvta_generic_to_shared(p);
}

// Lane-offset builders for ldmatrix address patterns (row stride 36 uints).
__device__ __forceinline__ int laneA_off(int L) {
    return ((((L >> 3) & 1) * 8 + (L & 7)) * 36 + (L >> 4) * 4) * 4;
}
__device__ __forceinline__ int laneB_off(int L) {
    return (((L >> 4) * 8 + (L & 7)) * 36 + ((L >> 3) & 1) * 4) * 4;
}

// ============================================================================
// Kernel 1: positional-encoding projections pe_q / pe_k  [1024, 64] (fp32)
// ============================================================================
__global__ void pe_proj_kernel(const float* __restrict__ Wpx, const float* __restrict__ bpx,
                               const float* __restrict__ Wpy, const float* __restrict__ bpy) {
    int p = blockIdx.x;
    int y = p >> 5, x = p & 31;
    const float* W = blockIdx.y ? Wpy : Wpx;
    const float* bb = blockIdx.y ? bpy : bpx;
    float* outp = blockIdx.y ? g_pek : g_peq;

    __shared__ float pe[CC];
    int c = threadIdx.x;
    {
        int pos = (c < 128) ? y : x;
        int idx = (c < 128) ? c : (c - 128);
        int j = idx >> 1;
        float ang = (float)pos * expf(-logf(10000.0f) * (float)j / 64.0f);
        pe[c] = (idx & 1) ? cosf(ang) : sinf(ang);
    }
    __syncthreads();
    if (c < AA) {
        float s = 0.0f;
        #pragma unroll 8
        for (int i = 0; i < CC; i++) s += pe[i] * W[c * CC + i];
        outp[p * AA + c] = s + bb[c];
    }
}

// ============================================================================
// proj body (device fn): tf32 GEMM -> bf16 outputs, register-pipelined loads.
// Uses dynamic smem: As = sm_[0..4351] (32x136), Ws = sm_[4352..6655] (64x36).
// ============================================================================
__device__ __forceinline__ void proj_body(uint32_t* sm_, int m0, int n0, int z,
                                          const float* __restrict__ A,
                                          const float* __restrict__ W,
                                          const float* __restrict__ bias,
                                          int N, int mode) {
    uint32_t (*As)[136] = (uint32_t(*)[136])sm_;
    uint32_t (*Ws)[36]  = (uint32_t(*)[36])(sm_ + 32 * 136);

    A += (size_t)z * CC * PP;

    int tid = threadIdx.x;
    int wid = tid >> 5;
    int g = (tid >> 2) & 7, tg = tid & 3;
    int mbase = (wid >> 1) * 32;
    int nbase = (wid & 1) * 32;

    float acc[2][4][4];
    #pragma unroll
    for (int i = 0; i < 2; i++)
        #pragma unroll
        for (int j = 0; j < 4; j++)
            #pragma unroll
            for (int r = 0; r < 4; r++) acc[i][j][r] = 0.0f;

    float4 ar[4], wr[2];
    auto ldA = [&](int c0) {
        #pragma unroll
        for (int i = 0; i < 4; i++) {
            int idx = i * 256 + tid;
            int row = idx >> 5, c4 = idx & 31;
            ar[i] = *(const float4*)&A[(size_t)(c0 + row) * PP + m0 + c4 * 4];
        }
    };
    auto ldW = [&](int c0) {
        #pragma unroll
        for (int i = 0; i < 2; i++) {
            int idx = i * 256 + tid;
            int row = idx >> 3, c4 = idx & 7;
            wr[i] = *(const float4*)&W[(size_t)(n0 + row) * CC + c0 + c4 * 4];
        }
    };

    ldA(0); ldW(0);

    for (int c0 = 0; c0 < CC; c0 += 32) {
        #pragma unroll
        for (int i = 0; i < 4; i++) {
            int idx = i * 256 + tid;
            int row = idx >> 5, c4 = idx & 31;
            *(uint4*)&As[row][c4 * 4] = cvt4(ar[i]);
        }
        #pragma unroll
        for (int i = 0; i < 2; i++) {
            int idx = i * 256 + tid;
            int row = idx >> 3, c4 = idx & 7;
            *(uint4*)&Ws[row][c4 * 4] = cvt4(wr[i]);
        }
        __syncthreads();

        if (c0 + 32 < CC) { ldA(c0 + 32); ldW(c0 + 32); }

        #pragma unroll
        for (int ks = 0; ks < 4; ks++) {
            int k0 = ks * 8;
            uint32_t af[2][4], bf[4][2];
            #pragma unroll
            for (int mt = 0; mt < 2; mt++) {
                int mr = mbase + mt * 16;
                af[mt][0] = As[k0 + tg][mr + g];
                af[mt][1] = As[k0 + tg][mr + g + 8];
                af[mt][2] = As[k0 + tg + 4][mr + g];
                af[mt][3] = As[k0 + tg + 4][mr + g + 8];
            }
            #pragma unroll
            for (int nt = 0; nt < 4; nt++) {
                int nr = nbase + nt * 8;
                bf[nt][0] = Ws[nr + g][k0 + tg];
                bf[nt][1] = Ws[nr + g][k0 + tg + 4];
            }
            #pragma unroll
            for (int mt = 0; mt < 2; mt++)
                #pragma unroll
                for (int nt = 0; nt < 4; nt++)
                    mma8(acc[mt][nt], af[mt], bf[nt]);
        }
        __syncthreads();
    }

    if (mode < 2) {
        const float* extra = (mode == 0) ? g_peq : g_pek;
        unsigned* C = (mode == 0 ? g_q : g_k) + (size_t)z * PP * (N / 2);
        #pragma unroll
        for (int mt = 0; mt < 2; mt++) {
            int r0 = m0 + mbase + mt * 16 + g;
            #pragma unroll
            for (int nt = 0; nt < 4; nt++) {
                int col = n0 + nbase + nt * 8 + 2 * tg;
                float b0 = bias[col], b1 = bias[col + 1];
                float e00 = extra[r0 * AA + col],       e01 = extra[r0 * AA + col + 1];
                float e10 = extra[(r0 + 8) * AA + col], e11 = extra[(r0 + 8) * AA + col + 1];
                C[r0 * (N / 2) + col / 2] =
                    pack_bf16(acc[mt][nt][0] + b0 + e00, acc[mt][nt][1] + b1 + e01);
                C[(r0 + 8) * (N / 2) + col / 2] =
                    pack_bf16(acc[mt][nt][2] + b0 + e10, acc[mt][nt][3] + b1 + e11);
            }
        }
    } else {
        __nv_bfloat16* Cs = (__nv_bfloat16*)sm_;   // 64 x 132 bf16 rows (66 uints)
        #pragma unroll
        for (int mt = 0; mt < 2; mt++) {
            int r0 = mbase + mt * 16 + g;
            #pragma unroll
            for (int nt = 0; nt < 4; nt++) {
                int col = nbase + nt * 8 + 2 * tg;
                float b0 = bias[n0 + col], b1 = bias[n0 + col + 1];
                Cs[(col)     * 132 + r0]     = __float2bfloat16(acc[mt][nt][0] + b0);
                Cs[(col + 1) * 132 + r0]     = __float2bfloat16(acc[mt][nt][1] + b1);
                Cs[(col)     * 132 + r0 + 8] = __float2bfloat16(acc[mt][nt][2] + b0);
                Cs[(col + 1) * 132 + r0 + 8] = __float2bfloat16(acc[mt][nt][3] + b1);
            }
        }
        __syncthreads();
        int b = z >> 3, page = z & 7;
        const unsigned* Csu = (const unsigned*)Cs;
        int tid2 = threadIdx.x;
        #pragma unroll
        for (int j = 0; j < 16; j++) {
            int f = j * 256 + tid2;
            int n = f >> 6, u = f & 63;
            g_vt[(size_t)(b * CC + n0 + n) * (NK / 2) + page * 512 + m0 / 2 + u] =
                Csu[n * 66 + u];
        }
    }
}

// ============================================================================
// qk body (device fn): QK^T (bf16, ldmatrix) + register-local batch softmax
// -> P (bf16), smem-staged coalesced writes. Dynamic smem: 18432 uints.
// ============================================================================
#define QK_TILE (4 * 64 * 36)
#define QK_SMEM_BYTES (2 * QK_TILE * 4)   // 73728 B

__device__ __forceinline__ void qk_body(uint32_t* sm_, int qtile, int ktile) {
    const uint32_t sb = smem_u32(sm_);

    const int tid = threadIdx.x;
    const int wid = tid >> 5;
    const int L = tid & 31;
    const int g = (tid >> 2) & 7, tg = tid & 3;
    const int qbase = qtile * 64, kbase = ktile * 64;

    #pragma unroll
    for (int j = 0; j < 8; j++) {
        int f = j * 256 + tid;
        int row = f >> 3, a4 = f & 7;
        int b = row >> 6, r = row & 63;
        cp_async16(sb + (row * 36 + a4 * 4) * 4,
                   &g_q[((b << 10) + qbase + r) * 32 + a4 * 4]);
        cp_async16(sb + (QK_TILE + row * 36 + a4 * 4) * 4,
                   &g_k[((b << 13) + kbase + r) * 32 + a4 * 4]);
    }
    CP_COMMIT();
    cp_wait<0>();
    __syncthreads();

    const int wm = wid >> 2, wn = wid & 3;
    const int qrow0 = wm * 32, kcol0 = wn * 16;

    const int aoff = laneA_off(L);
    const int boff = laneB_off(L);
    const uint32_t qa_base = sb + qrow0 * 36 * 4 + aoff;
    const uint32_t kb_base = sb + QK_TILE * 4 + kcol0 * 36 * 4 + boff;

    float acc[4][2][2][4];
    #pragma unroll
    for (int b = 0; b < 4; b++)
        #pragma unroll
        for (int i = 0; i < 2; i++)
            #pragma unroll
            for (int j = 0; j < 2; j++)
                #pragma unroll
                for (int r = 0; r < 4; r++) acc[b][i][j][r] = 0.0f;

    #pragma unroll
    for (int ks = 0; ks < 4; ks++) {
        int k0b = ks * 32;
        #pragma unroll
        for (int b = 0; b < 4; b++) {
            unsigned af[2][4], bf[4];
            ldm_x4(af[0], qa_base + b * 9216 + k0b);
            ldm_x4(af[1], qa_base + b * 9216 + 16 * 36 * 4 + k0b);
            ldm_x4(bf,    kb_base + b * 9216 + k0b);
            #pragma unroll
            for (int mt = 0; mt < 2; mt++)
                #pragma unroll
                for (int nt = 0; nt < 2; nt++)
                    mma16(acc[b][mt][nt], af[mt], bf + nt * 2);
        }
    }

    __syncthreads();
    uint32_t* Ps = sm_;

    #pragma unroll
    for (int mt = 0; mt < 2; mt++) {
        int lo = qrow0 + mt * 16 + g;
        #pragma unroll
        for (int nt = 0; nt < 2; nt++) {
            int cu = kcol0 / 2 + nt * 4 + tg;
            float p[4][4];
            #pragma unroll
            for (int r = 0; r < 4; r++) {
                float s0 = acc[0][mt][nt][r] * 0.125f;
                float s1 = acc[1][mt][nt][r] * 0.125f;
                float s2 = acc[2][mt][nt][r] * 0.125f;
                float s3 = acc[3][mt][nt][r] * 0.125f;
                float m = fmaxf(fmaxf(s0, s1), fmaxf(s2, s3));
                float e0 = __expf(s0 - m), e1 = __expf(s1 - m);
                float e2 = __expf(s2 - m), e3 = __expf(s3 - m);
                float rv = 1.0f / (e0 + e1 + e2 + e3);
                p[r][0] = e0 * rv; p[r][1] = e1 * rv;
                p[r][2] = e2 * rv; p[r][3] = e3 * rv;
            }
            #pragma unroll
            for (int b = 0; b < 4; b++) {
                Ps[b * 2304 + lo * 36 + cu]       = pack_bf16(p[0][b], p[1][b]);
                Ps[b * 2304 + (lo + 8) * 36 + cu] = pack_bf16(p[2][b], p[3][b]);
            }
        }
    }
    __syncthreads();

    #pragma unroll
    for (int j = 0; j < 8; j++) {
        int f = j * 256 + tid;
        int b = f >> 9, r = (f >> 3) & 63, q4 = f & 7;
        uint4 val = *(const uint4*)&Ps[b * 2304 + r * 36 + q4 * 4];
        *(uint4*)&g_P[(size_t)b * (PL / 2) + (size_t)(qbase + r) * (NK / 2) + kbase / 2 + q4 * 4] = val;
    }
}

// ============================================================================
// Kernel 2: merged proj_q + proj_k (288 blocks; both depend only on pe)
// ============================================================================
__global__ __launch_bounds__(256, 2) void projqk_kernel(
    const float* __restrict__ zx, const float* __restrict__ Wq, const float* __restrict__ bq,
    const float* __restrict__ zy, const float* __restrict__ Wk, const float* __restrict__ bk) {
    extern __shared__ uint32_t sm[];
    int id = blockIdx.x;
    if (id < 32) {
        // proj_q: grid (8,1,4)
        proj_body(sm, (id & 7) * 128, 0, id >> 3, zx, Wq, bq, 64, 0);
    } else {
        // proj_k: grid (8,1,32)
        int id2 = id - 32;
        proj_body(sm, (id2 & 7) * 128, 0, id2 >> 3, zy, Wk, bk, 64, 1);
    }
}

// ============================================================================
// Kernel 3: merged proj_v + qk_softmax (3072 blocks, interleaved 1:2 so every
// wave co-schedules both; proj_v is independent of qk, qk needs only q/k)
// ============================================================================
__global__ __launch_bounds__(256, 2) void projv_qk_kernel(
    const float* __restrict__ zy, const float* __restrict__ Wv, const float* __restrict__ bv) {
    extern __shared__ uint32_t sm[];
    int idx = blockIdx.x;
    if (idx % 3 == 0) {
        // proj_v: 1024 blocks, orig grid (8,4,32)
        int vid = idx / 3;
        proj_body(sm, (vid & 7) * 128, ((vid >> 3) & 3) * 64, vid >> 5, zy, Wv, bv, 256, 2);
    } else {
        // qk: 2048 blocks, orig grid (16,128)
        int qkid = idx - idx / 3 - 1;
        qk_body(sm, qkid & 15, qkid >> 4);
    }
}

// ============================================================================
// Kernel 4: O = P @ V (bf16, ldmatrix), split-K=4, BK=64, 3-stage pipeline.
// 2 CTAs/SM. BM=128, BN=128(c). 8 warps (4m x 2n). grid (8, 2, 16).
// ============================================================================
#define PS_BUF (128 * 36)
#define VS_BUF (128 * 36)
#define STAGE  (PS_BUF + VS_BUF)
#define PV_SMEM_BYTES (3 * STAGE * 4)   // 110592 B

__global__ __launch_bounds__(256, 2) void pv_mma() {
    extern __shared__ uint32_t sm[];
    const uint32_t sb = smem_u32(sm);

    int b = blockIdx.z >> 2;
    int split = blockIdx.z & 3;
    int m0 = blockIdx.x * 128, n0 = blockIdx.y * 128;
    int tid = threadIdx.x;
    int wid = tid >> 5;
    const int L = tid & 31;
    int g = (tid >> 2) & 7, tg = tid & 3;
    int mbase = (wid >> 1) * 32;
    int nbase = (wid & 1) * 64;

    const unsigned* Pu = g_P  + (size_t)b * (PL / 2);
    const unsigned* Vu = g_vt + (size_t)b * CC * (NK / 2);

    const int kstart = split * (NK / PVSPLIT);
    const int NIT = (NK / PVSPLIT) / 64;   // 32

    auto prefetch = [&](int it, int stage) {
        int kbu = (kstart + it * 64) / 2;
        #pragma unroll
        for (int j = 0; j < 4; j++) {
            int f = j * 256 + tid;
            int row = f >> 3, c4 = f & 7;
            uint32_t dst = sb + (stage * STAGE + row * 36 + c4 * 4) * 4;
            cp_async16(dst, Pu + (size_t)(m0 + row) * (NK / 2) + kbu + c4 * 4);
            uint32_t dst2 = sb + (stage * STAGE + PS_BUF + row * 36 + c4 * 4) * 4;
            cp_async16(dst2, Vu + (size_t)(n0 + row) * (NK / 2) + kbu + c4 * 4);
        }
        CP_COMMIT();
    };

    float acc[2][8][4];
    #pragma unroll
    for (int i = 0; i < 2; i++)
        #pragma unroll
        for (int j = 0; j < 8; j++)
            #pragma unroll
            for (int r = 0; r < 4; r++) acc[i][j][r] = 0.0f;

    const int aoff = laneA_off(L);
    const int boff = laneB_off(L);
    const uint32_t pa_base = sb + mbase * 36 * 4 + aoff;
    const uint32_t vb_base = sb + PS_BUF * 4 + nbase * 36 * 4 + boff;

    prefetch(0, 0);
    prefetch(1, 1);

    int stage = 0;
    for (int it = 0; it < NIT; it++) {
        if (it + 1 < NIT) cp_wait<1>(); else cp_wait<0>();
        __syncthreads();
        if (it + 2 < NIT) {
            int ns = stage + 2; if (ns >= 3) ns -= 3;
            prefetch(it + 2, ns);
        }

        uint32_t stg = (uint32_t)(stage * STAGE * 4);
        #pragma unroll
        for (int ks = 0; ks < 4; ks++) {
            int k0b = ks * 32;
            unsigned af[2][4], bf[4][4];
            ldm_x4(af[0], pa_base + stg + k0b);
            ldm_x4(af[1], pa_base + stg + 16 * 36 * 4 + k0b);
            #pragma unroll
            for (int j = 0; j < 4; j++)
                ldm_x4(bf[j], vb_base + stg + j * 16 * 36 * 4 + k0b);
            #pragma unroll
            for (int mt = 0; mt < 2; mt++)
                #pragma unroll
                for (int nt = 0; nt < 8; nt++)
                    mma16(acc[mt][nt], af[mt], bf[nt >> 1] + (nt & 1) * 2);
        }
        if (++stage == 3) stage = 0;
    }

    float* part = g_part + (size_t)split * (BB * PP * CC);
    #pragma unroll
    for (int mt = 0; mt < 2; mt++) {
        int r0 = m0 + mbase + mt * 16 + g;
        #pragma unroll
        for (int nt = 0; nt < 8; nt++) {
            int col = n0 + nbase + nt * 8 + 2 * tg;
            __stcs((float2*)&part[(size_t)((b << 10) + r0) * CC + col],
                   make_float2(acc[mt][nt][0], acc[mt][nt][1]));
            __stcs((float2*)&part[(size_t)((b << 10) + r0 + 8) * CC + col],
                   make_float2(acc[mt][nt][2], acc[mt][nt][3]));
        }
    }
}

// ============================================================================
// Kernel 5: deterministic 4-way split-K reduction into d_out ([b][p][c])
// ============================================================================
__global__ void reduce4(float* __restrict__ out) {
    int i = blockIdx.x * blockDim.x + threadIdx.x;
    const float4* p = (const float4*)g_part;
    const int plane = BB * PP * CC / 4;
    float4 s = __ldcs(p + i);
    #pragma unroll
    for (int sp = 1; sp < PVSPLIT; sp++) {
        float4 t = __ldcs(p + (size_t)sp * plane + i);
        s.x += t.x; s.y += t.y; s.z += t.z; s.w += t.w;
    }
    ((float4*)out)[i] = s;
}

// ============================================================================
extern "C" void kernel_launch(void* const* d_in, const int* in_sizes, int n_in,
                              void* d_out, int out_size) {
    const float* zx  = (const float*)d_in[0];
    const float* zy  = (const float*)d_in[1];
    const float* Wq  = (const float*)d_in[2];
    const float* bq  = (const float*)d_in[3];
    const float* Wpx = (const float*)d_in[4];
    const float* bpx = (const float*)d_in[5];
    const float* Wk  = (const float*)d_in[6];
    const float* bk  = (const float*)d_in[7];
    const float* Wpy = (const float*)d_in[8];
    const float* bpy = (const float*)d_in[9];
    const float* Wv  = (const float*)d_in[10];
    const float* bv  = (const float*)d_in[11];
    float* out = (float*)d_out;

    const int proj_smem = 32 * 136 * 4 + 64 * 36 * 4;   // 26624 B
    cudaFuncSetAttribute(projqk_kernel, cudaFuncAttributeMaxDynamicSharedMemorySize,
                         proj_smem);
    cudaFuncSetAttribute(projv_qk_kernel, cudaFuncAttributeMaxDynamicSharedMemorySize,
                         QK_SMEM_BYTES);
    cudaFuncSetAttribute(pv_mma, cudaFuncAttributeMaxDynamicSharedMemorySize,
                         PV_SMEM_BYTES);

    pe_proj_kernel<<<dim3(PP, 2), CC>>>(Wpx, bpx, Wpy, bpy);
    projqk_kernel<<<288, 256, proj_smem>>>(zx, Wq, bq, zy, Wk, bk);
    projv_qk_kernel<<<3072, 256, QK_SMEM_BYTES>>>(zy, Wv, bv);
    pv_mma<<<dim3(8, 2, 16), 256, PV_SMEM_BYTES>>>();
    reduce4<<<(BB * PP * CC / 4) / 256, 256>>>(out);
}